// round 1
// baseline (speedup 1.0000x reference)
#include <cuda_runtime.h>
#include <math.h>

#define Bb 2
#define Ss 2048
#define Dd 1024
#define Hh 16
#define DK 64
#define FFd 4096
#define ROWS (Bb*Ss)          // 4096
#define NEGV (-1000000000.0f)

// ---------------- scratch (no allocations allowed) ----------------
__device__ float g_n [ROWS*Dd];
__device__ float g_q [ROWS*Dd];
__device__ float g_k [ROWS*Dd];
__device__ float g_v [ROWS*Dd];
__device__ float g_o [ROWS*Dd];
__device__ float g_x1[ROWS*Dd];
__device__ float g_n2[ROWS*Dd];
__device__ float g_ff[ROWS*FFd];

// ---------------- layernorm: one block per row ----------------
__global__ void ln_kernel(const float* __restrict__ x,
                          const float* __restrict__ g,
                          const float* __restrict__ b,
                          float* __restrict__ o) {
    int row = blockIdx.x;
    const float* xr = x + (size_t)row * Dd;
    int tid = threadIdx.x;                 // 256 threads
    int lane = tid & 31, warp = tid >> 5;
    __shared__ float red[32];

    float lv[4]; float s = 0.f;
#pragma unroll
    for (int i = 0; i < 4; i++) { lv[i] = xr[tid + i*256]; s += lv[i]; }
#pragma unroll
    for (int off = 16; off; off >>= 1) s += __shfl_down_sync(0xffffffffu, s, off);
    if (lane == 0) red[warp] = s;
    __syncthreads();
    if (tid == 0) {
        float t = 0.f;
        for (int w = 0; w < 8; w++) t += red[w];
        red[0] = t;
    }
    __syncthreads();
    float mu = red[0] * (1.0f / Dd);
    __syncthreads();

    float vs = 0.f;
#pragma unroll
    for (int i = 0; i < 4; i++) { float d = lv[i] - mu; vs += d * d; }
#pragma unroll
    for (int off = 16; off; off >>= 1) vs += __shfl_down_sync(0xffffffffu, vs, off);
    if (lane == 0) red[warp] = vs;
    __syncthreads();
    if (tid == 0) {
        float t = 0.f;
        for (int w = 0; w < 8; w++) t += red[w];
        red[0] = t;
    }
    __syncthreads();
    float inv = rsqrtf(red[0] * (1.0f / Dd) + 1e-5f);

    float* orow = o + (size_t)row * Dd;
#pragma unroll
    for (int i = 0; i < 4; i++) {
        int c = tid + i * 256;
        orow[c] = (lv[i] - mu) * inv * g[c] + b[c];
    }
}

// ---------------- tiled fp32 GEMM: C[M,N] = A[M,K] @ W[K,N] + bias, epilogue opts --------
// BM=BN=64, BK=16, 256 threads, 4x4 microtile per thread.
template<bool DO_GELU, bool DO_RES>
__global__ void gemm_kernel(const float* __restrict__ A, const float* __restrict__ W,
                            const float* __restrict__ bias, const float* __restrict__ res,
                            float* __restrict__ C, int M, int N, int K) {
    __shared__ float As[16][65];   // [k][m], padded
    __shared__ float Ws[16][64];   // [k][n]
    int tid = threadIdx.x;
    int tx = tid & 15, ty = tid >> 4;
    int rowBase = blockIdx.y * 64;
    int colBase = blockIdx.x * 64;

    float acc[4][4] = {};

    for (int kk = 0; kk < K; kk += 16) {
#pragma unroll
        for (int i = 0; i < 4; i++) {
            int idx = tid + i * 256;
            int r = idx >> 4, c = idx & 15;
            As[c][r] = A[(size_t)(rowBase + r) * K + kk + c];
        }
#pragma unroll
        for (int i = 0; i < 4; i++) {
            int idx = tid + i * 256;
            int r = idx >> 6, c = idx & 63;
            Ws[r][c] = W[(size_t)(kk + r) * N + colBase + c];
        }
        __syncthreads();
#pragma unroll
        for (int k = 0; k < 16; k++) {
            float a[4], w[4];
#pragma unroll
            for (int i = 0; i < 4; i++) a[i] = As[k][ty * 4 + i];
#pragma unroll
            for (int j = 0; j < 4; j++) w[j] = Ws[k][tx * 4 + j];
#pragma unroll
            for (int i = 0; i < 4; i++)
#pragma unroll
                for (int j = 0; j < 4; j++)
                    acc[i][j] = fmaf(a[i], w[j], acc[i][j]);
        }
        __syncthreads();
    }

#pragma unroll
    for (int i = 0; i < 4; i++) {
        int row = rowBase + ty * 4 + i;
#pragma unroll
        for (int j = 0; j < 4; j++) {
            int col = colBase + tx * 4 + j;
            float v = acc[i][j] + bias[col];
            if (DO_GELU) v = 0.5f * v * (1.0f + erff(v * 0.70710678118654752f));
            if (DO_RES)  v += res[(size_t)row * N + col];
            C[(size_t)row * N + col] = v;
        }
    }
}

// ---------------- sparse attention: one block per (b,h,i) ----------------
// allowed j: j<=i and (i-j<=128 or (i-j)%128==0)  ->  <=129 local + <=14 strided keys
__global__ void attn_kernel(const float* __restrict__ q, const float* __restrict__ k,
                            const float* __restrict__ v, const int* __restrict__ mask,
                            float* __restrict__ o) {
    int idx = blockIdx.x;
    int i = idx & (Ss - 1);
    int h = (idx >> 11) & (Hh - 1);
    int b = idx >> 15;

    __shared__ float qs[DK];
    __shared__ float sc[160];
    __shared__ int   jl[160];
    __shared__ float redm[4], reds[4];

    int tid = threadIdx.x;           // 128
    int lane = tid & 31, warp = tid >> 5;

    const float* qrow = q + ((size_t)b * Ss + i) * Dd + h * DK;
    if (tid < DK) qs[tid] = qrow[tid];

    int nLocal = min(i, 128) + 1;
    int nStr   = max(0, i / 128 - 1);
    int nK     = nLocal + nStr;
    for (int t = tid; t < nK; t += 128)
        jl[t] = (t < nLocal) ? (i - t) : (i - 128 * (t - nLocal + 2));
    __syncthreads();

    // scores: one warp per key
    for (int t = warp; t < nK; t += 4) {
        int j = jl[t];
        const float* krow = k + ((size_t)b * Ss + j) * Dd + h * DK;
        float p = qs[lane] * krow[lane] + qs[lane + 32] * krow[lane + 32];
#pragma unroll
        for (int off = 16; off; off >>= 1) p += __shfl_down_sync(0xffffffffu, p, off);
        if (lane == 0) {
            float s = p * 0.125f;
            if (mask[(size_t)i * Ss + j] == 0) s = NEGV;
            sc[t] = s;
        }
    }
    __syncthreads();

    // softmax over sc[0..nK)
    float m = -3.0e38f;
    for (int t = tid; t < nK; t += 128) m = fmaxf(m, sc[t]);
#pragma unroll
    for (int off = 16; off; off >>= 1) m = fmaxf(m, __shfl_down_sync(0xffffffffu, m, off));
    if (lane == 0) redm[warp] = m;
    __syncthreads();
    m = fmaxf(fmaxf(redm[0], redm[1]), fmaxf(redm[2], redm[3]));

    float sum = 0.f;
    for (int t = tid; t < nK; t += 128) { float e = expf(sc[t] - m); sc[t] = e; sum += e; }
#pragma unroll
    for (int off = 16; off; off >>= 1) sum += __shfl_down_sync(0xffffffffu, sum, off);
    if (lane == 0) reds[warp] = sum;
    __syncthreads();
    float inv = 1.0f / (reds[0] + reds[1] + reds[2] + reds[3]);

    // PV: 64 threads, each owns one output dim
    if (tid < DK) {
        float acc = 0.f;
        for (int t = 0; t < nK; t++) {
            const float* vrow = v + ((size_t)b * Ss + jl[t]) * Dd + h * DK;
            acc += sc[t] * vrow[tid];
        }
        o[((size_t)b * Ss + i) * Dd + h * DK + tid] = acc * inv;
    }
}

// ---------------- launch ----------------
extern "C" void kernel_launch(void* const* d_in, const int* in_sizes, int n_in,
                              void* d_out, int out_size) {
    const float* x   = (const float*)d_in[0];
    const int*   msk = (const int*)  d_in[1];
    const float* Wq  = (const float*)d_in[2],  *bq  = (const float*)d_in[3];
    const float* Wk  = (const float*)d_in[4],  *bk  = (const float*)d_in[5];
    const float* Wv  = (const float*)d_in[6],  *bv  = (const float*)d_in[7];
    const float* Wo  = (const float*)d_in[8],  *bo  = (const float*)d_in[9];
    const float* W1  = (const float*)d_in[10], *bf1 = (const float*)d_in[11];
    const float* W2  = (const float*)d_in[12], *bf2 = (const float*)d_in[13];
    const float* g1  = (const float*)d_in[14], *bl1 = (const float*)d_in[15];
    const float* g2  = (const float*)d_in[16], *bl2 = (const float*)d_in[17];
    float* out = (float*)d_out;

    float *n_, *q_, *k_, *v_, *o_, *x1_, *n2_, *ff_;
    cudaGetSymbolAddress((void**)&n_,  g_n);
    cudaGetSymbolAddress((void**)&q_,  g_q);
    cudaGetSymbolAddress((void**)&k_,  g_k);
    cudaGetSymbolAddress((void**)&v_,  g_v);
    cudaGetSymbolAddress((void**)&o_,  g_o);
    cudaGetSymbolAddress((void**)&x1_, g_x1);
    cudaGetSymbolAddress((void**)&n2_, g_n2);
    cudaGetSymbolAddress((void**)&ff_, g_ff);

    dim3 gD(Dd / 64, ROWS / 64);    // N=1024
    dim3 gF(FFd / 64, ROWS / 64);   // N=4096

    // 1. pre-LN 1
    ln_kernel<<<ROWS, 256>>>(x, g1, bl1, n_);
    // 2. QKV projections
    gemm_kernel<false, false><<<gD, 256>>>(n_, Wq, bq, nullptr, q_, ROWS, Dd, Dd);
    gemm_kernel<false, false><<<gD, 256>>>(n_, Wk, bk, nullptr, k_, ROWS, Dd, Dd);
    gemm_kernel<false, false><<<gD, 256>>>(n_, Wv, bv, nullptr, v_, ROWS, Dd, Dd);
    // 3. sparse attention
    attn_kernel<<<Bb * Hh * Ss, 128>>>(q_, k_, v_, msk, o_);
    // 4. output projection + residual
    gemm_kernel<false, true><<<gD, 256>>>(o_, Wo, bo, x, x1_, ROWS, Dd, Dd);
    // 5. pre-LN 2
    ln_kernel<<<ROWS, 256>>>(x1_, g2, bl2, n2_);
    // 6. FFN up + exact GELU
    gemm_kernel<true, false><<<gF, 256>>>(n2_, W1, bf1, nullptr, ff_, ROWS, FFd, Dd);
    // 7. FFN down + residual -> out
    gemm_kernel<false, true><<<gD, 256>>>(ff_, W2, bf2, x1_, out, ROWS, Dd, FFd);
}

// round 2
// speedup vs baseline: 1.1004x; 1.1004x over previous
#include <cuda_runtime.h>
#include <cuda_bf16.h>
#include <math.h>

#define Bb 2
#define Ss 2048
#define Dd 1024
#define Hh 16
#define DK 64
#define FFd 4096
#define ROWS (Bb*Ss)          // 4096
#define NEGV (-1000000000.0f)
#define PAD 40

typedef __nv_bfloat16 bf16;

// ---------------- scratch (no allocations allowed) ----------------
__device__ __align__(256) float g_q [ROWS*Dd];
__device__ __align__(256) float g_k [ROWS*Dd];
__device__ __align__(256) float g_v [ROWS*Dd];
__device__ __align__(256) float g_x1[ROWS*Dd];
__device__ __align__(256) bf16 g_sa_h[ROWS*Dd];   // split of n / o / n2 (sequential reuse)
__device__ __align__(256) bf16 g_sa_l[ROWS*Dd];
__device__ __align__(256) bf16 g_sf_h[ROWS*FFd];  // split of ff
__device__ __align__(256) bf16 g_sf_l[ROWS*FFd];
__device__ __align__(256) bf16 g_wh [Dd*FFd];     // split of current weight
__device__ __align__(256) bf16 g_wl [Dd*FFd];

__device__ __forceinline__ void split1(float v, bf16* h, bf16* l, size_t idx) {
    bf16 hv = __float2bfloat16(v);
    h[idx] = hv;
    l[idx] = __float2bfloat16(v - __bfloat162float(hv));
}

// ---------------- weight split: fp32 -> (hi, lo) bf16 ----------------
__global__ void wsplit_kernel(const float* __restrict__ w,
                              bf16* __restrict__ h, bf16* __restrict__ l, int n) {
    int i = (blockIdx.x * 256 + threadIdx.x) * 4;
    if (i < n) {
        float4 v = *(const float4*)(w + i);
        split1(v.x, h, l, i + 0);
        split1(v.y, h, l, i + 1);
        split1(v.z, h, l, i + 2);
        split1(v.w, h, l, i + 3);
    }
}

// ---------------- layernorm (fused split output) ----------------
__global__ void ln_split_kernel(const float* __restrict__ x,
                                const float* __restrict__ g,
                                const float* __restrict__ b,
                                bf16* __restrict__ oh, bf16* __restrict__ ol) {
    int row = blockIdx.x;
    const float* xr = x + (size_t)row * Dd;
    int tid = threadIdx.x;                 // 256 threads
    int lane = tid & 31, warp = tid >> 5;
    __shared__ float red[32];

    float lv[4]; float s = 0.f;
#pragma unroll
    for (int i = 0; i < 4; i++) { lv[i] = xr[tid + i*256]; s += lv[i]; }
#pragma unroll
    for (int off = 16; off; off >>= 1) s += __shfl_down_sync(0xffffffffu, s, off);
    if (lane == 0) red[warp] = s;
    __syncthreads();
    if (tid == 0) {
        float t = 0.f;
        for (int w = 0; w < 8; w++) t += red[w];
        red[0] = t;
    }
    __syncthreads();
    float mu = red[0] * (1.0f / Dd);
    __syncthreads();

    float vs = 0.f;
#pragma unroll
    for (int i = 0; i < 4; i++) { float d = lv[i] - mu; vs += d * d; }
#pragma unroll
    for (int off = 16; off; off >>= 1) vs += __shfl_down_sync(0xffffffffu, vs, off);
    if (lane == 0) red[warp] = vs;
    __syncthreads();
    if (tid == 0) {
        float t = 0.f;
        for (int w = 0; w < 8; w++) t += red[w];
        red[0] = t;
    }
    __syncthreads();
    float inv = rsqrtf(red[0] * (1.0f / Dd) + 1e-5f);

#pragma unroll
    for (int i = 0; i < 4; i++) {
        int c = tid + i * 256;
        float v = (lv[i] - mu) * inv * g[c] + b[c];
        split1(v, oh, ol, (size_t)row * Dd + c);
    }
}

// ---------------- bf16 split-precision tensor-core GEMM ----------------
// C[M,N] = (Ah+Al)[M,K] @ (Bh+Bl)[K,N] + bias  (+gelu) (+res)
// BM=128, BN=128, BK=32, 256 threads (8 warps, 2x4), warp tile 64x32, mma m16n8k16.
#define MMA_OP(d, a, b) asm volatile( \
    "mma.sync.aligned.m16n8k16.row.col.f32.bf16.bf16.f32 " \
    "{%0,%1,%2,%3}, {%4,%5,%6,%7}, {%8,%9}, {%0,%1,%2,%3};\n" \
    : "+f"(d[0]), "+f"(d[1]), "+f"(d[2]), "+f"(d[3]) \
    : "r"(a[0]), "r"(a[1]), "r"(a[2]), "r"(a[3]), "r"(b[0]), "r"(b[1]))

template<bool DO_GELU, bool DO_RES, bool OUT_SPLIT>
__global__ __launch_bounds__(256, 1)
void bgemm(const bf16* __restrict__ Ah, const bf16* __restrict__ Al,
           const bf16* __restrict__ Bh, const bf16* __restrict__ Bl,
           const float* __restrict__ bias, const float* __restrict__ res,
           float* __restrict__ C, bf16* __restrict__ Ch, bf16* __restrict__ Cl,
           int M, int N, int K) {
    __shared__ __align__(16) bf16 sAh[128][PAD], sAl[128][PAD];
    __shared__ __align__(16) bf16 sBh[128][PAD], sBl[128][PAD];
    int tid = threadIdx.x, lane = tid & 31, warp = tid >> 5;
    int wm = warp >> 2, wn = warp & 3;     // 2 x 4 warps
    int rowBase = blockIdx.y * 128, colBase = blockIdx.x * 128;

    float acc[4][4][4] = {};
    uint4 rAh[2], rAl[2], rBh[2], rBl[2];

    auto loadG = [&](int kk) {
#pragma unroll
        for (int i = 0; i < 2; i++) {
            int ch = tid + i * 256; int r = ch >> 2, c = (ch & 3) * 8;
            const bf16* pa = Ah + (size_t)(rowBase + r) * K + kk + c;
            const bf16* pl = Al + (size_t)(rowBase + r) * K + kk + c;
            rAh[i] = *(const uint4*)pa;
            rAl[i] = *(const uint4*)pl;
        }
#pragma unroll
        for (int i = 0; i < 2; i++) {
            int ch = tid + i * 256; int kr = ch >> 4, c = (ch & 15) * 8;
            const bf16* pb = Bh + (size_t)(kk + kr) * N + colBase + c;
            const bf16* pl = Bl + (size_t)(kk + kr) * N + colBase + c;
            rBh[i] = *(const uint4*)pb;
            rBl[i] = *(const uint4*)pl;
        }
    };
    auto storeS = [&]() {
#pragma unroll
        for (int i = 0; i < 2; i++) {
            int ch = tid + i * 256; int r = ch >> 2, c = (ch & 3) * 8;
            *(uint4*)&sAh[r][c] = rAh[i];
            *(uint4*)&sAl[r][c] = rAl[i];
        }
#pragma unroll
        for (int i = 0; i < 2; i++) {
            int ch = tid + i * 256; int kr = ch >> 4, c = (ch & 15) * 8;
            bf16 th[8], tl[8];
            *(uint4*)th = rBh[i];
            *(uint4*)tl = rBl[i];
#pragma unroll
            for (int j = 0; j < 8; j++) { sBh[c + j][kr] = th[j]; sBl[c + j][kr] = tl[j]; }
        }
    };

    loadG(0); storeS(); __syncthreads();
    int NT = K / 32;
    for (int t = 0; t < NT; t++) {
        if (t + 1 < NT) loadG((t + 1) * 32);
#pragma unroll
        for (int ks = 0; ks < 2; ks++) {
            int ko = ks * 16;
            unsigned fAh[4][4], fAl[4][4], fBh[4][2], fBl[4][2];
#pragma unroll
            for (int mi = 0; mi < 4; mi++) {
                int r = wm * 64 + mi * 16 + (lane >> 2);
                int c = ko + (lane & 3) * 2;
                fAh[mi][0] = *(const unsigned*)&sAh[r][c];
                fAh[mi][1] = *(const unsigned*)&sAh[r + 8][c];
                fAh[mi][2] = *(const unsigned*)&sAh[r][c + 8];
                fAh[mi][3] = *(const unsigned*)&sAh[r + 8][c + 8];
                fAl[mi][0] = *(const unsigned*)&sAl[r][c];
                fAl[mi][1] = *(const unsigned*)&sAl[r + 8][c];
                fAl[mi][2] = *(const unsigned*)&sAl[r][c + 8];
                fAl[mi][3] = *(const unsigned*)&sAl[r + 8][c + 8];
            }
#pragma unroll
            for (int ni = 0; ni < 4; ni++) {
                int nr = wn * 32 + ni * 8 + (lane >> 2);
                int kc = ko + (lane & 3) * 2;
                fBh[ni][0] = *(const unsigned*)&sBh[nr][kc];
                fBh[ni][1] = *(const unsigned*)&sBh[nr][kc + 8];
                fBl[ni][0] = *(const unsigned*)&sBl[nr][kc];
                fBl[ni][1] = *(const unsigned*)&sBl[nr][kc + 8];
            }
#pragma unroll
            for (int mi = 0; mi < 4; mi++)
#pragma unroll
                for (int ni = 0; ni < 4; ni++) {
                    MMA_OP(acc[mi][ni], fAh[mi], fBh[ni]);
                    MMA_OP(acc[mi][ni], fAh[mi], fBl[ni]);
                    MMA_OP(acc[mi][ni], fAl[mi], fBh[ni]);
                }
        }
        __syncthreads();
        if (t + 1 < NT) { storeS(); __syncthreads(); }
    }

    // epilogue
#pragma unroll
    for (int mi = 0; mi < 4; mi++)
#pragma unroll
        for (int ni = 0; ni < 4; ni++) {
            int r = rowBase + wm * 64 + mi * 16 + (lane >> 2);
            int c = colBase + wn * 32 + ni * 8 + (lane & 3) * 2;
#pragma unroll
            for (int p = 0; p < 2; p++) {
                int rr = r + p * 8;
#pragma unroll
                for (int qi = 0; qi < 2; qi++) {
                    float v = acc[mi][ni][p * 2 + qi] + bias[c + qi];
                    if (DO_GELU) v = 0.5f * v * (1.0f + erff(v * 0.70710678118654752f));
                    if (DO_RES)  v += res[(size_t)rr * N + c + qi];
                    if (OUT_SPLIT) {
                        bf16 hv = __float2bfloat16(v);
                        Ch[(size_t)rr * N + c + qi] = hv;
                        Cl[(size_t)rr * N + c + qi] = __float2bfloat16(v - __bfloat162float(hv));
                    } else {
                        C[(size_t)rr * N + c + qi] = v;
                    }
                }
            }
        }
}

// ---------------- sparse attention: one block per (b,h,i); split output ----------------
__global__ void attn_kernel(const float* __restrict__ q, const float* __restrict__ k,
                            const float* __restrict__ v, const int* __restrict__ mask,
                            bf16* __restrict__ oh, bf16* __restrict__ ol) {
    int idx = blockIdx.x;
    int i = idx & (Ss - 1);
    int h = (idx >> 11) & (Hh - 1);
    int b = idx >> 15;

    __shared__ float qs[DK];
    __shared__ float sc[160];
    __shared__ int   jl[160];
    __shared__ float redm[4], reds[4];

    int tid = threadIdx.x;           // 128
    int lane = tid & 31, warp = tid >> 5;

    const float* qrow = q + ((size_t)b * Ss + i) * Dd + h * DK;
    if (tid < DK) qs[tid] = qrow[tid];

    int nLocal = min(i, 128) + 1;
    int nStr   = max(0, i / 128 - 1);
    int nK     = nLocal + nStr;
    for (int t = tid; t < nK; t += 128)
        jl[t] = (t < nLocal) ? (i - t) : (i - 128 * (t - nLocal + 2));
    __syncthreads();

    for (int t = warp; t < nK; t += 4) {
        int j = jl[t];
        const float* krow = k + ((size_t)b * Ss + j) * Dd + h * DK;
        float p = qs[lane] * krow[lane] + qs[lane + 32] * krow[lane + 32];
#pragma unroll
        for (int off = 16; off; off >>= 1) p += __shfl_down_sync(0xffffffffu, p, off);
        if (lane == 0) {
            float s = p * 0.125f;
            if (mask[(size_t)i * Ss + j] == 0) s = NEGV;
            sc[t] = s;
        }
    }
    __syncthreads();

    float m = -3.0e38f;
    for (int t = tid; t < nK; t += 128) m = fmaxf(m, sc[t]);
#pragma unroll
    for (int off = 16; off; off >>= 1) m = fmaxf(m, __shfl_down_sync(0xffffffffu, m, off));
    if (lane == 0) redm[warp] = m;
    __syncthreads();
    m = fmaxf(fmaxf(redm[0], redm[1]), fmaxf(redm[2], redm[3]));

    float sum = 0.f;
    for (int t = tid; t < nK; t += 128) { float e = expf(sc[t] - m); sc[t] = e; sum += e; }
#pragma unroll
    for (int off = 16; off; off >>= 1) sum += __shfl_down_sync(0xffffffffu, sum, off);
    if (lane == 0) reds[warp] = sum;
    __syncthreads();
    float inv = 1.0f / (reds[0] + reds[1] + reds[2] + reds[3]);

    if (tid < DK) {
        float acc = 0.f;
        for (int t = 0; t < nK; t++) {
            const float* vrow = v + ((size_t)b * Ss + jl[t]) * Dd + h * DK;
            acc += sc[t] * vrow[tid];
        }
        float val = acc * inv;
        size_t oidx = ((size_t)b * Ss + i) * Dd + h * DK + tid;
        bf16 hv = __float2bfloat16(val);
        oh[oidx] = hv;
        ol[oidx] = __float2bfloat16(val - __bfloat162float(hv));
    }
}

// ---------------- launch ----------------
extern "C" void kernel_launch(void* const* d_in, const int* in_sizes, int n_in,
                              void* d_out, int out_size) {
    const float* x   = (const float*)d_in[0];
    const int*   msk = (const int*)  d_in[1];
    const float* Wq  = (const float*)d_in[2],  *bq  = (const float*)d_in[3];
    const float* Wk  = (const float*)d_in[4],  *bk  = (const float*)d_in[5];
    const float* Wv  = (const float*)d_in[6],  *bv  = (const float*)d_in[7];
    const float* Wo  = (const float*)d_in[8],  *bo  = (const float*)d_in[9];
    const float* W1  = (const float*)d_in[10], *bf1 = (const float*)d_in[11];
    const float* W2  = (const float*)d_in[12], *bf2 = (const float*)d_in[13];
    const float* g1  = (const float*)d_in[14], *bl1 = (const float*)d_in[15];
    const float* g2  = (const float*)d_in[16], *bl2 = (const float*)d_in[17];
    float* out = (float*)d_out;

    float *q_, *k_, *v_, *x1_;
    bf16 *sah, *sal, *sfh, *sfl, *wh, *wl;
    cudaGetSymbolAddress((void**)&q_,  g_q);
    cudaGetSymbolAddress((void**)&k_,  g_k);
    cudaGetSymbolAddress((void**)&v_,  g_v);
    cudaGetSymbolAddress((void**)&x1_, g_x1);
    cudaGetSymbolAddress((void**)&sah, g_sa_h);
    cudaGetSymbolAddress((void**)&sal, g_sa_l);
    cudaGetSymbolAddress((void**)&sfh, g_sf_h);
    cudaGetSymbolAddress((void**)&sfl, g_sf_l);
    cudaGetSymbolAddress((void**)&wh,  g_wh);
    cudaGetSymbolAddress((void**)&wl,  g_wl);

    const int nDD = Dd * Dd;       // 1M
    const int nDF = Dd * FFd;      // 4M
    dim3 gD(Dd / 128, ROWS / 128);   // 8 x 32
    dim3 gF(FFd / 128, ROWS / 128);  // 32 x 32

    // 1. pre-LN 1 -> split(n)
    ln_split_kernel<<<ROWS, 256>>>(x, g1, bl1, sah, sal);

    // 2. QKV projections (bf16 TC)
    wsplit_kernel<<<nDD / 1024, 256>>>(Wq, wh, wl, nDD);
    bgemm<false, false, false><<<gD, 256>>>(sah, sal, wh, wl, bq, nullptr, q_, nullptr, nullptr, ROWS, Dd, Dd);
    wsplit_kernel<<<nDD / 1024, 256>>>(Wk, wh, wl, nDD);
    bgemm<false, false, false><<<gD, 256>>>(sah, sal, wh, wl, bk, nullptr, k_, nullptr, nullptr, ROWS, Dd, Dd);
    wsplit_kernel<<<nDD / 1024, 256>>>(Wv, wh, wl, nDD);
    bgemm<false, false, false><<<gD, 256>>>(sah, sal, wh, wl, bv, nullptr, v_, nullptr, nullptr, ROWS, Dd, Dd);

    // 3. sparse attention -> split(o) (overwrites n split, which is now dead)
    attn_kernel<<<Bb * Hh * Ss, 128>>>(q_, k_, v_, msk, sah, sal);

    // 4. output projection + residual -> x1 (fp32)
    wsplit_kernel<<<nDD / 1024, 256>>>(Wo, wh, wl, nDD);
    bgemm<false, true, false><<<gD, 256>>>(sah, sal, wh, wl, bo, x, x1_, nullptr, nullptr, ROWS, Dd, Dd);

    // 5. pre-LN 2 -> split(n2)
    ln_split_kernel<<<ROWS, 256>>>(x1_, g2, bl2, sah, sal);

    // 6. FFN up + GELU -> split(ff)  (no fp32 intermediate)
    wsplit_kernel<<<nDF / 1024, 256>>>(W1, wh, wl, nDF);
    bgemm<true, false, true><<<gF, 256>>>(sah, sal, wh, wl, bf1, nullptr, nullptr, sfh, sfl, ROWS, FFd, Dd);

    // 7. FFN down + residual -> out
    wsplit_kernel<<<nDF / 1024, 256>>>(W2, wh, wl, nDF);
    bgemm<false, true, false><<<gD, 256>>>(sfh, sfl, wh, wl, bf2, x1_, out, nullptr, nullptr, ROWS, Dd, FFd);
}

// round 6
// speedup vs baseline: 1.8814x; 1.7098x over previous
#include <cuda_runtime.h>
#include <cuda_bf16.h>
#include <math.h>
#include <stdint.h>

#define Bb 2
#define Ss 2048
#define Dd 1024
#define Hh 16
#define DK 64
#define FFd 4096
#define ROWS (Bb*Ss)          // 4096
#define NEGV (-1000000000.0f)
typedef __nv_bfloat16 bf16;

// ---------------- scratch ----------------
__device__ __align__(256) float g_qkv[ROWS*3*Dd];   // fused q|k|v fp32
__device__ __align__(256) float g_x1 [ROWS*Dd];
__device__ __align__(256) bf16  g_sa_h[ROWS*Dd];    // split of n / o / n2 (sequential reuse)
__device__ __align__(256) bf16  g_sa_l[ROWS*Dd];
__device__ __align__(256) bf16  g_sf_h[ROWS*FFd];   // split of ff
__device__ __align__(256) bf16  g_sf_l[ROWS*FFd];
__device__ __align__(256) bf16  g_wth[Dd*FFd];      // transposed+split weight [N][K]
__device__ __align__(256) bf16  g_wtl[Dd*FFd];
__device__ __align__(256) float g_bcat[3*Dd];

__device__ __forceinline__ void split1(float v, bf16* h, bf16* l, size_t idx) {
    bf16 hv = __float2bfloat16(v);
    h[idx] = hv;
    l[idx] = __float2bfloat16(v - __bfloat162float(hv));
}

// ---------------- weight transpose + split: W[K,N] fp32 -> Wt[N,K] bf16 hi/lo ---------
__global__ void wtsplit_kernel(const float* __restrict__ W,
                               bf16* __restrict__ th, bf16* __restrict__ tl,
                               int K, int N, int rowOff) {
    __shared__ float tile[32][33];
    int kk = blockIdx.y * 32, nn = blockIdx.x * 32;
    int tx = threadIdx.x, ty = threadIdx.y;   // 32 x 8
#pragma unroll
    for (int i = 0; i < 4; i++)
        tile[ty + 8*i][tx] = W[(size_t)(kk + ty + 8*i) * N + nn + tx];
    __syncthreads();
#pragma unroll
    for (int i = 0; i < 4; i++) {
        float v = tile[tx][ty + 8*i];         // = W[kk+tx][nn+ty+8i]
        size_t o = (size_t)(rowOff + nn + ty + 8*i) * K + kk + tx;
        split1(v, th, tl, o);
    }
}

// ---------------- bias concat for fused QKV ----------------
__global__ void bcat_kernel(const float* __restrict__ bq, const float* __restrict__ bk,
                            const float* __restrict__ bv, float* __restrict__ o) {
    int i = blockIdx.x * 256 + threadIdx.x;
    if (i < 3*Dd)
        o[i] = (i < Dd) ? bq[i] : ((i < 2*Dd) ? bk[i - Dd] : bv[i - 2*Dd]);
}

// ---------------- layernorm (fused split output) ----------------
__global__ void ln_split_kernel(const float* __restrict__ x,
                                const float* __restrict__ g,
                                const float* __restrict__ b,
                                bf16* __restrict__ oh, bf16* __restrict__ ol) {
    int row = blockIdx.x;
    const float* xr = x + (size_t)row * Dd;
    int tid = threadIdx.x;                 // 256 threads
    int lane = tid & 31, warp = tid >> 5;
    __shared__ float red[32];

    float lv[4]; float s = 0.f;
#pragma unroll
    for (int i = 0; i < 4; i++) { lv[i] = xr[tid + i*256]; s += lv[i]; }
#pragma unroll
    for (int off = 16; off; off >>= 1) s += __shfl_down_sync(0xffffffffu, s, off);
    if (lane == 0) red[warp] = s;
    __syncthreads();
    if (tid == 0) { float t = 0.f; for (int w = 0; w < 8; w++) t += red[w]; red[0] = t; }
    __syncthreads();
    float mu = red[0] * (1.0f / Dd);
    __syncthreads();

    float vs = 0.f;
#pragma unroll
    for (int i = 0; i < 4; i++) { float d = lv[i] - mu; vs += d * d; }
#pragma unroll
    for (int off = 16; off; off >>= 1) vs += __shfl_down_sync(0xffffffffu, vs, off);
    if (lane == 0) red[warp] = vs;
    __syncthreads();
    if (tid == 0) { float t = 0.f; for (int w = 0; w < 8; w++) t += red[w]; red[0] = t; }
    __syncthreads();
    float inv = rsqrtf(red[0] * (1.0f / Dd) + 1e-5f);

#pragma unroll
    for (int i = 0; i < 4; i++) {
        int c = tid + i * 256;
        float v = (lv[i] - mu) * inv * g[c] + b[c];
        split1(v, oh, ol, (size_t)row * Dd + c);
    }
}

// ---------------- HMMA split-bf16 GEMM (ldmatrix + cp.async 4-stage) ----------------
// C[M,N] = (Ah+Al)[M,K] @ (Bh+Bl)[N,K]^T + bias (+gelu) (+res)
// BM=128, BN=128, BK=32, 256 threads (8 warps 2x4), warp tile 64x32.
#define RS 80                       // smem row stride (bytes) for 64B rows: conflict-free
#define ARR (128*RS)                // 10240 B per array
#define STG (4*ARR)                 // 40960 B per stage (Ah|Al|Bh|Bl)
#define NSTAGE 4
#define GEMM_SMEM (NSTAGE*STG)      // 163840

__device__ __forceinline__ void cp16(uint32_t s, const void* g) {
    asm volatile("cp.async.cg.shared.global [%0], [%1], 16;" :: "r"(s), "l"(g) : "memory");
}
#define LDSM4(r, a) asm volatile( \
    "ldmatrix.sync.aligned.m8n8.x4.shared.b16 {%0,%1,%2,%3}, [%4];" \
    : "=r"((r)[0]), "=r"((r)[1]), "=r"((r)[2]), "=r"((r)[3]) : "r"(a))
#define MMA_OP(d, a, b0, b1) asm volatile( \
    "mma.sync.aligned.m16n8k16.row.col.f32.bf16.bf16.f32 " \
    "{%0,%1,%2,%3}, {%4,%5,%6,%7}, {%8,%9}, {%0,%1,%2,%3};\n" \
    : "+f"((d)[0]), "+f"((d)[1]), "+f"((d)[2]), "+f"((d)[3]) \
    : "r"((a)[0]), "r"((a)[1]), "r"((a)[2]), "r"((a)[3]), "r"(b0), "r"(b1))

template<bool DO_GELU, bool DO_RES, bool OSPLIT>
__global__ __launch_bounds__(256)
void bgemm_mma(const bf16* __restrict__ Ah, const bf16* __restrict__ Al,
               const bf16* __restrict__ Bh, const bf16* __restrict__ Bl,
               const float* __restrict__ bias, const float* __restrict__ res,
               float* __restrict__ C, bf16* __restrict__ Ch, bf16* __restrict__ Cl,
               int M, int N, int K) {
    extern __shared__ __align__(128) char smem[];
    const int tid = threadIdx.x, lane = tid & 31, warp = tid >> 5;
    const int wm = warp >> 2, wn = warp & 3;
    const int rowBase = blockIdx.y * 128, colBase = blockIdx.x * 128;
    const uint32_t sb = (uint32_t)__cvta_generic_to_shared(smem);
    const int NS = K >> 5;

    auto issue = [&](int s) {
        uint32_t st = sb + (uint32_t)(s & 3) * STG;
        int kk = s << 5;
#pragma unroll
        for (int j = 0; j < 2; j++) {
            int c = tid + (j << 8);                  // 0..511 chunk id
            int r = c >> 2, ke = (c & 3) << 3;       // row, k-elem offset
            uint32_t dst = st + r * RS + ((c & 3) << 4);
            size_t ga = (size_t)(rowBase + r) * K + kk + ke;
            size_t gb = (size_t)(colBase + r) * K + kk + ke;
            cp16(dst,           Ah + ga);
            cp16(dst +   ARR,   Al + ga);
            cp16(dst + 2*ARR,   Bh + gb);
            cp16(dst + 3*ARR,   Bl + gb);
        }
        asm volatile("cp.async.commit_group;" ::: "memory");
    };

    float acc[4][4][4] = {};   // [mi][n8][4]

    issue(0); issue(1); issue(2);

    for (int s = 0; s < NS; s++) {
        int rem = NS - 1 - s;
        if (rem >= 2)      asm volatile("cp.async.wait_group 2;" ::: "memory");
        else if (rem == 1) asm volatile("cp.async.wait_group 1;" ::: "memory");
        else               asm volatile("cp.async.wait_group 0;" ::: "memory");
        __syncthreads();
        if (s + 3 < NS) issue(s + 3);

        uint32_t st = sb + (uint32_t)(s & 3) * STG;
        uint32_t aBase = st + (wm * 64 + (lane & 15)) * RS + ((lane >> 4) << 4);
        uint32_t bBase = st + 2*ARR + (wn * 32 + (lane & 15)) * RS + ((lane >> 4) << 4);
#pragma unroll
        for (int ks = 0; ks < 2; ks++) {
            uint32_t ko = ks * 32;   // 16 elems * 2B
            uint32_t ah[4][4], alr[4][4], bh[2][4], blr[2][4];
#pragma unroll
            for (int mi = 0; mi < 4; mi++) {
                LDSM4(ah[mi],  aBase + mi * (16*RS) + ko);
                LDSM4(alr[mi], aBase + ARR + mi * (16*RS) + ko);
            }
#pragma unroll
            for (int nb = 0; nb < 2; nb++) {
                LDSM4(bh[nb],  bBase + nb * (16*RS) + ko);
                LDSM4(blr[nb], bBase + ARR + nb * (16*RS) + ko);
            }
#pragma unroll
            for (int mi = 0; mi < 4; mi++)
#pragma unroll
                for (int nb = 0; nb < 2; nb++)
#pragma unroll
                    for (int g = 0; g < 2; g++) {
                        float* d = acc[mi][nb*2 + g];
                        MMA_OP(d, ah[mi],  bh[nb][g],  bh[nb][g+2]);
                        MMA_OP(d, ah[mi],  blr[nb][g], blr[nb][g+2]);
                        MMA_OP(d, alr[mi], bh[nb][g],  bh[nb][g+2]);
                    }
        }
        __syncthreads();
    }

    // ---- epilogue ----
#pragma unroll
    for (int mi = 0; mi < 4; mi++) {
        int r0 = rowBase + wm * 64 + mi * 16 + (lane >> 2);
#pragma unroll
        for (int n8 = 0; n8 < 4; n8++) {
            // fragment n-range: wn*32 + (n8>>1)*16 + (n8&1)*8
            int c = colBase + wn * 32 + (n8 >> 1) * 16 + (n8 & 1) * 8 + (lane & 3) * 2;
            float* d = acc[mi][n8];
            float b0 = bias[c], b1 = bias[c + 1];
#pragma unroll
            for (int p = 0; p < 2; p++) {
                int r = r0 + p * 8;
                float v0 = d[p*2]     + b0;
                float v1 = d[p*2 + 1] + b1;
                if (DO_GELU) {
                    v0 = 0.5f * v0 * (1.0f + erff(v0 * 0.70710678118654752f));
                    v1 = 0.5f * v1 * (1.0f + erff(v1 * 0.70710678118654752f));
                }
                if (DO_RES) {
                    float2 rr = *(const float2*)(res + (size_t)r * N + c);
                    v0 += rr.x; v1 += rr.y;
                }
                if (OSPLIT) {
                    bf16 h0 = __float2bfloat16(v0), h1 = __float2bfloat16(v1);
                    bf16 l0 = __float2bfloat16(v0 - __bfloat162float(h0));
                    bf16 l1 = __float2bfloat16(v1 - __bfloat162float(h1));
                    uint32_t hp = ((uint32_t)*(uint16_t*)&h1 << 16) | *(uint16_t*)&h0;
                    uint32_t lp = ((uint32_t)*(uint16_t*)&l1 << 16) | *(uint16_t*)&l0;
                    *(uint32_t*)(Ch + (size_t)r * N + c) = hp;
                    *(uint32_t*)(Cl + (size_t)r * N + c) = lp;
                } else {
                    *(float2*)(C + (size_t)r * N + c) = make_float2(v0, v1);
                }
            }
        }
    }
}

// ---------------- sparse attention (fused qkv layout, split output) ----------------
__global__ void attn_kernel(const float* __restrict__ qkv, const int* __restrict__ mask,
                            bf16* __restrict__ oh, bf16* __restrict__ ol) {
    int idx = blockIdx.x;
    int i = idx & (Ss - 1);
    int h = (idx >> 11) & (Hh - 1);
    int b = idx >> 15;

    __shared__ float qs[DK];
    __shared__ float sc[160];
    __shared__ int   jl[160];
    __shared__ float redm[4], reds[4];

    int tid = threadIdx.x;           // 128
    int lane = tid & 31, warp = tid >> 5;

    const float* qrow = qkv + ((size_t)b * Ss + i) * (3*Dd) + h * DK;
    if (tid < DK) qs[tid] = qrow[tid];

    int nLocal = min(i, 128) + 1;
    int nStr   = max(0, i / 128 - 1);
    int nK     = nLocal + nStr;
    for (int t = tid; t < nK; t += 128)
        jl[t] = (t < nLocal) ? (i - t) : (i - 128 * (t - nLocal + 2));
    __syncthreads();

    for (int t = warp; t < nK; t += 4) {
        int j = jl[t];
        const float* krow = qkv + ((size_t)b * Ss + j) * (3*Dd) + Dd + h * DK;
        float p = qs[lane] * krow[lane] + qs[lane + 32] * krow[lane + 32];
#pragma unroll
        for (int off = 16; off; off >>= 1) p += __shfl_down_sync(0xffffffffu, p, off);
        if (lane == 0) {
            float s = p * 0.125f;
            if (mask[(size_t)i * Ss + j] == 0) s = NEGV;
            sc[t] = s;
        }
    }
    __syncthreads();

    float m = -3.0e38f;
    for (int t = tid; t < nK; t += 128) m = fmaxf(m, sc[t]);
#pragma unroll
    for (int off = 16; off; off >>= 1) m = fmaxf(m, __shfl_down_sync(0xffffffffu, m, off));
    if (lane == 0) redm[warp] = m;
    __syncthreads();
    m = fmaxf(fmaxf(redm[0], redm[1]), fmaxf(redm[2], redm[3]));

    float sum = 0.f;
    for (int t = tid; t < nK; t += 128) { float e = expf(sc[t] - m); sc[t] = e; sum += e; }
#pragma unroll
    for (int off = 16; off; off >>= 1) sum += __shfl_down_sync(0xffffffffu, sum, off);
    if (lane == 0) reds[warp] = sum;
    __syncthreads();
    float inv = 1.0f / (reds[0] + reds[1] + reds[2] + reds[3]);

    if (tid < DK) {
        float acc = 0.f;
        for (int t = 0; t < nK; t++) {
            const float* vrow = qkv + ((size_t)b * Ss + jl[t]) * (3*Dd) + 2*Dd + h * DK;
            acc += sc[t] * vrow[tid];
        }
        float val = acc * inv;
        size_t oidx = ((size_t)b * Ss + i) * Dd + h * DK + tid;
        bf16 hv = __float2bfloat16(val);
        oh[oidx] = hv;
        ol[oidx] = __float2bfloat16(val - __bfloat162float(hv));
    }
}

// ---------------- launch ----------------
extern "C" void kernel_launch(void* const* d_in, const int* in_sizes, int n_in,
                              void* d_out, int out_size) {
    const float* x   = (const float*)d_in[0];
    const int*   msk = (const int*)  d_in[1];
    const float* Wq  = (const float*)d_in[2],  *bq  = (const float*)d_in[3];
    const float* Wk  = (const float*)d_in[4],  *bk  = (const float*)d_in[5];
    const float* Wv  = (const float*)d_in[6],  *bv  = (const float*)d_in[7];
    const float* Wo  = (const float*)d_in[8],  *bo  = (const float*)d_in[9];
    const float* W1  = (const float*)d_in[10], *bf1 = (const float*)d_in[11];
    const float* W2  = (const float*)d_in[12], *bf2 = (const float*)d_in[13];
    const float* g1  = (const float*)d_in[14], *bl1 = (const float*)d_in[15];
    const float* g2  = (const float*)d_in[16], *bl2 = (const float*)d_in[17];
    float* out = (float*)d_out;

    float *qkv_, *x1_, *bcat_;
    bf16 *sah, *sal, *sfh, *sfl, *wth, *wtl;
    cudaGetSymbolAddress((void**)&qkv_, g_qkv);
    cudaGetSymbolAddress((void**)&x1_,  g_x1);
    cudaGetSymbolAddress((void**)&bcat_,g_bcat);
    cudaGetSymbolAddress((void**)&sah,  g_sa_h);
    cudaGetSymbolAddress((void**)&sal,  g_sa_l);
    cudaGetSymbolAddress((void**)&sfh,  g_sf_h);
    cudaGetSymbolAddress((void**)&sfl,  g_sf_l);
    cudaGetSymbolAddress((void**)&wth,  g_wth);
    cudaGetSymbolAddress((void**)&wtl,  g_wtl);

    cudaFuncSetAttribute(bgemm_mma<false, false, false>,
                         cudaFuncAttributeMaxDynamicSharedMemorySize, GEMM_SMEM);
    cudaFuncSetAttribute(bgemm_mma<false, true, false>,
                         cudaFuncAttributeMaxDynamicSharedMemorySize, GEMM_SMEM);
    cudaFuncSetAttribute(bgemm_mma<true, false, true>,
                         cudaFuncAttributeMaxDynamicSharedMemorySize, GEMM_SMEM);

    dim3 wgrid(Dd / 32, Dd / 32);
    dim3 wblk(32, 8);

    // pre-LN 1 -> split(n)
    ln_split_kernel<<<ROWS, 256>>>(x, g1, bl1, sah, sal);

    // fused QKV: Wt = [3072][1024]
    bcat_kernel<<<12, 256>>>(bq, bk, bv, bcat_);
    wtsplit_kernel<<<wgrid, wblk>>>(Wq, wth, wtl, Dd, Dd, 0);
    wtsplit_kernel<<<wgrid, wblk>>>(Wk, wth, wtl, Dd, Dd, Dd);
    wtsplit_kernel<<<wgrid, wblk>>>(Wv, wth, wtl, Dd, Dd, 2*Dd);
    bgemm_mma<false, false, false><<<dim3(3*Dd/128, ROWS/128), 256, GEMM_SMEM>>>(
        sah, sal, wth, wtl, bcat_, nullptr, qkv_, nullptr, nullptr, ROWS, 3*Dd, Dd);

    // sparse attention -> split(o)
    attn_kernel<<<Bb * Hh * Ss, 128>>>(qkv_, msk, sah, sal);

    // output projection + residual -> x1
    wtsplit_kernel<<<wgrid, wblk>>>(Wo, wth, wtl, Dd, Dd, 0);
    bgemm_mma<false, true, false><<<dim3(Dd/128, ROWS/128), 256, GEMM_SMEM>>>(
        sah, sal, wth, wtl, bo, x, x1_, nullptr, nullptr, ROWS, Dd, Dd);

    // pre-LN 2 -> split(n2)
    ln_split_kernel<<<ROWS, 256>>>(x1_, g2, bl2, sah, sal);

    // FFN up + GELU -> split(ff);  Wt1 = [4096][1024]
    wtsplit_kernel<<<dim3(FFd/32, Dd/32), wblk>>>(W1, wth, wtl, Dd, FFd, 0);
    bgemm_mma<true, false, true><<<dim3(FFd/128, ROWS/128), 256, GEMM_SMEM>>>(
        sah, sal, wth, wtl, bf1, nullptr, nullptr, sfh, sfl, ROWS, FFd, Dd);

    // FFN down + residual -> out;  Wt2 = [1024][4096]
    wtsplit_kernel<<<dim3(Dd/32, FFd/32), wblk>>>(W2, wth, wtl, FFd, Dd, 0);
    bgemm_mma<false, true, false><<<dim3(Dd/128, ROWS/128), 256, GEMM_SMEM>>>(
        sfh, sfl, wth, wtl, bf2, x1_, out, nullptr, nullptr, ROWS, Dd, FFd);
}

// round 7
// speedup vs baseline: 2.1306x; 1.1325x over previous
#include <cuda_runtime.h>
#include <cuda_bf16.h>
#include <math.h>
#include <stdint.h>

#define Bb 2
#define Ss 2048
#define Dd 1024
#define Hh 16
#define DK 64
#define FFd 4096
#define ROWS (Bb*Ss)          // 4096
#define NEGV (-1000000000.0f)
typedef __nv_bfloat16 bf16;

// ---------------- scratch ----------------
__device__ __align__(256) float g_qkv[ROWS*3*Dd];   // fused q|k|v fp32
__device__ __align__(256) float g_x1 [ROWS*Dd];
__device__ __align__(256) bf16  g_sa_h[ROWS*Dd];    // split of n / o / n2 (sequential reuse)
__device__ __align__(256) bf16  g_sa_l[ROWS*Dd];
__device__ __align__(256) bf16  g_sf_h[ROWS*FFd];   // split of ff
__device__ __align__(256) bf16  g_sf_l[ROWS*FFd];
__device__ __align__(256) bf16  g_wth[Dd*FFd];      // transposed+split weight [N][K]
__device__ __align__(256) bf16  g_wtl[Dd*FFd];
__device__ __align__(256) float g_bcat[3*Dd];

__device__ __forceinline__ void split1(float v, bf16* h, bf16* l, size_t idx) {
    bf16 hv = __float2bfloat16(v);
    h[idx] = hv;
    l[idx] = __float2bfloat16(v - __bfloat162float(hv));
}

// ---------------- weight transpose + split: W[K,N] fp32 -> Wt[N,K] bf16 hi/lo ---------
__device__ __forceinline__ void wtsplit_body(const float* __restrict__ W,
                                             bf16* __restrict__ th, bf16* __restrict__ tl,
                                             int K, int N, int rowOff,
                                             float (*tile)[33]) {
    int kk = blockIdx.y * 32, nn = blockIdx.x * 32;
    int tx = threadIdx.x, ty = threadIdx.y;   // 32 x 8
#pragma unroll
    for (int i = 0; i < 4; i++)
        tile[ty + 8*i][tx] = W[(size_t)(kk + ty + 8*i) * N + nn + tx];
    __syncthreads();
#pragma unroll
    for (int i = 0; i < 4; i++) {
        float v = tile[tx][ty + 8*i];         // = W[kk+tx][nn+ty+8i]
        size_t o = (size_t)(rowOff + nn + ty + 8*i) * K + kk + tx;
        split1(v, th, tl, o);
    }
}
__global__ void wtsplit_kernel(const float* __restrict__ W,
                               bf16* __restrict__ th, bf16* __restrict__ tl,
                               int K, int N, int rowOff) {
    __shared__ float tile[32][33];
    wtsplit_body(W, th, tl, K, N, rowOff, tile);
}
__global__ void wtsplit3_kernel(const float* __restrict__ W0, const float* __restrict__ W1,
                                const float* __restrict__ W2,
                                bf16* __restrict__ th, bf16* __restrict__ tl) {
    __shared__ float tile[32][33];
    const float* W = (blockIdx.z == 0) ? W0 : (blockIdx.z == 1) ? W1 : W2;
    wtsplit_body(W, th, tl, Dd, Dd, blockIdx.z * Dd, tile);
}

// ---------------- bias concat for fused QKV ----------------
__global__ void bcat_kernel(const float* __restrict__ bq, const float* __restrict__ bk,
                            const float* __restrict__ bv, float* __restrict__ o) {
    int i = blockIdx.x * 256 + threadIdx.x;
    if (i < 3*Dd)
        o[i] = (i < Dd) ? bq[i] : ((i < 2*Dd) ? bk[i - Dd] : bv[i - 2*Dd]);
}

// ---------------- layernorm (fused split output) ----------------
__global__ void ln_split_kernel(const float* __restrict__ x,
                                const float* __restrict__ g,
                                const float* __restrict__ b,
                                bf16* __restrict__ oh, bf16* __restrict__ ol) {
    int row = blockIdx.x;
    const float* xr = x + (size_t)row * Dd;
    int tid = threadIdx.x;                 // 256 threads
    int lane = tid & 31, warp = tid >> 5;
    __shared__ float red[32];

    float lv[4]; float s = 0.f;
#pragma unroll
    for (int i = 0; i < 4; i++) { lv[i] = xr[tid + i*256]; s += lv[i]; }
#pragma unroll
    for (int off = 16; off; off >>= 1) s += __shfl_down_sync(0xffffffffu, s, off);
    if (lane == 0) red[warp] = s;
    __syncthreads();
    if (tid == 0) { float t = 0.f; for (int w = 0; w < 8; w++) t += red[w]; red[0] = t; }
    __syncthreads();
    float mu = red[0] * (1.0f / Dd);
    __syncthreads();

    float vs = 0.f;
#pragma unroll
    for (int i = 0; i < 4; i++) { float d = lv[i] - mu; vs += d * d; }
#pragma unroll
    for (int off = 16; off; off >>= 1) vs += __shfl_down_sync(0xffffffffu, vs, off);
    if (lane == 0) red[warp] = vs;
    __syncthreads();
    if (tid == 0) { float t = 0.f; for (int w = 0; w < 8; w++) t += red[w]; red[0] = t; }
    __syncthreads();
    float inv = rsqrtf(red[0] * (1.0f / Dd) + 1e-5f);

#pragma unroll
    for (int i = 0; i < 4; i++) {
        int c = tid + i * 256;
        float v = (lv[i] - mu) * inv * g[c] + b[c];
        split1(v, oh, ol, (size_t)row * Dd + c);
    }
}

// ---------------- HMMA split-bf16 GEMM (ldmatrix + cp.async 4-stage) ----------------
#define RS 80
#define ARR (128*RS)
#define STG (4*ARR)
#define NSTAGE 4
#define GEMM_SMEM (NSTAGE*STG)      // 163840

__device__ __forceinline__ void cp16(uint32_t s, const void* g) {
    asm volatile("cp.async.cg.shared.global [%0], [%1], 16;" :: "r"(s), "l"(g) : "memory");
}
#define LDSM4(r, a) asm volatile( \
    "ldmatrix.sync.aligned.m8n8.x4.shared.b16 {%0,%1,%2,%3}, [%4];" \
    : "=r"((r)[0]), "=r"((r)[1]), "=r"((r)[2]), "=r"((r)[3]) : "r"(a))
#define MMA_OP(d, a, b0, b1) asm volatile( \
    "mma.sync.aligned.m16n8k16.row.col.f32.bf16.bf16.f32 " \
    "{%0,%1,%2,%3}, {%4,%5,%6,%7}, {%8,%9}, {%0,%1,%2,%3};\n" \
    : "+f"((d)[0]), "+f"((d)[1]), "+f"((d)[2]), "+f"((d)[3]) \
    : "r"((a)[0]), "r"((a)[1]), "r"((a)[2]), "r"((a)[3]), "r"(b0), "r"(b1))

template<bool DO_GELU, bool DO_RES, bool OSPLIT>
__global__ __launch_bounds__(256)
void bgemm_mma(const bf16* __restrict__ Ah, const bf16* __restrict__ Al,
               const bf16* __restrict__ Bh, const bf16* __restrict__ Bl,
               const float* __restrict__ bias, const float* __restrict__ res,
               float* __restrict__ C, bf16* __restrict__ Ch, bf16* __restrict__ Cl,
               int M, int N, int K) {
    extern __shared__ __align__(128) char smem[];
    const int tid = threadIdx.x, lane = tid & 31, warp = tid >> 5;
    const int wm = warp >> 2, wn = warp & 3;
    const int rowBase = blockIdx.y * 128, colBase = blockIdx.x * 128;
    const uint32_t sb = (uint32_t)__cvta_generic_to_shared(smem);
    const int NS = K >> 5;

    auto issue = [&](int s) {
        uint32_t st = sb + (uint32_t)(s & 3) * STG;
        int kk = s << 5;
#pragma unroll
        for (int j = 0; j < 2; j++) {
            int c = tid + (j << 8);
            int r = c >> 2, ke = (c & 3) << 3;
            uint32_t dst = st + r * RS + ((c & 3) << 4);
            size_t ga = (size_t)(rowBase + r) * K + kk + ke;
            size_t gb = (size_t)(colBase + r) * K + kk + ke;
            cp16(dst,           Ah + ga);
            cp16(dst +   ARR,   Al + ga);
            cp16(dst + 2*ARR,   Bh + gb);
            cp16(dst + 3*ARR,   Bl + gb);
        }
        asm volatile("cp.async.commit_group;" ::: "memory");
    };

    float acc[4][4][4] = {};

    issue(0); issue(1); issue(2);

    for (int s = 0; s < NS; s++) {
        if (s + 3 < NS) issue(s + 3);
        int rem = NS - 1 - s;
        if (rem >= 3)      asm volatile("cp.async.wait_group 3;" ::: "memory");
        else if (rem == 2) asm volatile("cp.async.wait_group 2;" ::: "memory");
        else if (rem == 1) asm volatile("cp.async.wait_group 1;" ::: "memory");
        else               asm volatile("cp.async.wait_group 0;" ::: "memory");
        __syncthreads();

        uint32_t st = sb + (uint32_t)(s & 3) * STG;
        uint32_t aBase = st + (wm * 64 + (lane & 15)) * RS + ((lane >> 4) << 4);
        uint32_t bBase = st + 2*ARR + (wn * 32 + (lane & 15)) * RS + ((lane >> 4) << 4);
#pragma unroll
        for (int ks = 0; ks < 2; ks++) {
            uint32_t ko = ks * 32;
            uint32_t ah[4][4], alr[4][4], bh[2][4], blr[2][4];
#pragma unroll
            for (int mi = 0; mi < 4; mi++) {
                LDSM4(ah[mi],  aBase + mi * (16*RS) + ko);
                LDSM4(alr[mi], aBase + ARR + mi * (16*RS) + ko);
            }
#pragma unroll
            for (int nb = 0; nb < 2; nb++) {
                LDSM4(bh[nb],  bBase + nb * (16*RS) + ko);
                LDSM4(blr[nb], bBase + ARR + nb * (16*RS) + ko);
            }
#pragma unroll
            for (int mi = 0; mi < 4; mi++)
#pragma unroll
                for (int nb = 0; nb < 2; nb++)
#pragma unroll
                    for (int g = 0; g < 2; g++) {
                        float* d = acc[mi][nb*2 + g];
                        MMA_OP(d, ah[mi],  bh[nb][g],  bh[nb][g+2]);
                        MMA_OP(d, ah[mi],  blr[nb][g], blr[nb][g+2]);
                        MMA_OP(d, alr[mi], bh[nb][g],  bh[nb][g+2]);
                    }
        }
        __syncthreads();
    }

    // ---- epilogue ----
#pragma unroll
    for (int mi = 0; mi < 4; mi++) {
        int r0 = rowBase + wm * 64 + mi * 16 + (lane >> 2);
#pragma unroll
        for (int n8 = 0; n8 < 4; n8++) {
            int c = colBase + wn * 32 + (n8 >> 1) * 16 + (n8 & 1) * 8 + (lane & 3) * 2;
            float* d = acc[mi][n8];
            float b0 = bias[c], b1 = bias[c + 1];
#pragma unroll
            for (int p = 0; p < 2; p++) {
                int r = r0 + p * 8;
                float v0 = d[p*2]     + b0;
                float v1 = d[p*2 + 1] + b1;
                if (DO_GELU) {
                    v0 = 0.5f * v0 * (1.0f + erff(v0 * 0.70710678118654752f));
                    v1 = 0.5f * v1 * (1.0f + erff(v1 * 0.70710678118654752f));
                }
                if (DO_RES) {
                    float2 rr = *(const float2*)(res + (size_t)r * N + c);
                    v0 += rr.x; v1 += rr.y;
                }
                if (OSPLIT) {
                    bf16 h0 = __float2bfloat16(v0), h1 = __float2bfloat16(v1);
                    bf16 l0 = __float2bfloat16(v0 - __bfloat162float(h0));
                    bf16 l1 = __float2bfloat16(v1 - __bfloat162float(h1));
                    uint32_t hp = ((uint32_t)*(uint16_t*)&h1 << 16) | *(uint16_t*)&h0;
                    uint32_t lp = ((uint32_t)*(uint16_t*)&l1 << 16) | *(uint16_t*)&l0;
                    *(uint32_t*)(Ch + (size_t)r * N + c) = hp;
                    *(uint32_t*)(Cl + (size_t)r * N + c) = lp;
                } else {
                    *(float2*)(C + (size_t)r * N + c) = make_float2(v0, v1);
                }
            }
        }
    }
}

// ---------------- query-tile flash sparse attention ----------------
// 1 block per (qtile, h, b): 128 queries. Dense tiles {qb-1, qb} (simple
// predicates), strided older tiles contribute only the diagonal element,
// read directly from L2. Online softmax; thread = (query, 32-dim half).
#define KST 68                       // smem row stride (floats) for K/V: 16B aligned
#define PST 130
#define ATT_SMEM ((2*128*KST + 128*PST) * 4)   // 136192 B

__global__ __launch_bounds__(256)
void attn2_kernel(const float* __restrict__ qkv, const int* __restrict__ mask,
                  bf16* __restrict__ oh, bf16* __restrict__ ol) {
    extern __shared__ float sm[];
    float* Ks = sm;
    float* Vs = sm + 128*KST;
    float* Ps = sm + 2*128*KST;

    const int qb = blockIdx.x, h = blockIdx.y, b = blockIdx.z;
    const int tid = threadIdx.x;
    const int qi = tid >> 1, half = tid & 1;
    const int i = qb * 128 + qi;
    const float scale = 0.125f;
    const int* mrow = mask + (size_t)i * Ss;

    // q row -> registers
    float qreg[64];
    {
        const float* qptr = qkv + ((size_t)b * Ss + i) * (3*Dd) + h * DK;
#pragma unroll
        for (int d4 = 0; d4 < 16; d4++) {
            float4 v = *(const float4*)(qptr + 4*d4);
            qreg[4*d4] = v.x; qreg[4*d4+1] = v.y; qreg[4*d4+2] = v.z; qreg[4*d4+3] = v.w;
        }
    }

    float m = -3.0e38f, l = 0.f;
    float o[32];
#pragma unroll
    for (int d = 0; d < 32; d++) o[d] = 0.f;

    // ---- strided (diagonal) tiles: offsets 2..qb ----
    for (int mm = 2; mm <= qb; mm++) {
        int j = i - 128 * mm;
        const float* kr = qkv + ((size_t)b * Ss + j) * (3*Dd) + Dd + h * DK + half * 32;
        float s0 = 0, s1 = 0, s2 = 0, s3 = 0;
#pragma unroll
        for (int d4 = 0; d4 < 8; d4++) {
            float4 kv = *(const float4*)(kr + 4*d4);
            s0 += qreg[half*32 + 4*d4]     * kv.x;
            s1 += qreg[half*32 + 4*d4 + 1] * kv.y;
            s2 += qreg[half*32 + 4*d4 + 2] * kv.z;
            s3 += qreg[half*32 + 4*d4 + 3] * kv.w;
        }
        float sc = (s0 + s1) + (s2 + s3);
        sc += __shfl_xor_sync(0xffffffffu, sc, 1);
        sc *= scale;
        if (mrow[j] == 0) sc = NEGV;

        float mn = fmaxf(m, sc);
        float corr = __expf(m - mn);
        float p = __expf(sc - mn);
        l = l * corr + (half ? 0.f : p);      // pair adds p once
        m = mn;
        const float* vr = qkv + ((size_t)b * Ss + j) * (3*Dd) + 2*Dd + h * DK + half * 32;
#pragma unroll
        for (int d4 = 0; d4 < 8; d4++) {
            float4 vv = *(const float4*)(vr + 4*d4);
            o[4*d4]   = o[4*d4]   * corr + p * vv.x;
            o[4*d4+1] = o[4*d4+1] * corr + p * vv.y;
            o[4*d4+2] = o[4*d4+2] * corr + p * vv.z;
            o[4*d4+3] = o[4*d4+3] * corr + p * vv.w;
        }
    }

    // ---- dense tiles ----
    int t0 = (qb > 0) ? qb - 1 : 0;
    for (int t = t0; t <= qb; t++) {
        __syncthreads();
        const float* gk = qkv + ((size_t)b * Ss + t*128) * (3*Dd) + Dd + h * DK;
        const float* gv = gk + Dd;
        for (int idx = tid; idx < 8192; idx += 256) {
            int r = idx >> 6, d = idx & 63;
            Ks[r*KST + d] = gk[(size_t)r * (3*Dd) + d];
            Vs[r*KST + d] = gv[(size_t)r * (3*Dd) + d];
        }
        __syncthreads();

        // scores for kj = half*64 + c
        float tmax = -3.0e38f;
        int jbase = t * 128;
        for (int c = 0; c < 64; c++) {
            int kj = half*64 + c;
            bool allowed = (t == qb) ? (kj <= qi) : (kj >= qi);
            float sc = NEGV;
            if (allowed && mrow[jbase + kj] != 0) {
                const float* kr = &Ks[kj*KST];
                float s0 = 0, s1 = 0, s2 = 0, s3 = 0;
#pragma unroll
                for (int d4 = 0; d4 < 16; d4++) {
                    float4 kv = *(const float4*)(kr + 4*d4);
                    s0 += qreg[4*d4]   * kv.x;
                    s1 += qreg[4*d4+1] * kv.y;
                    s2 += qreg[4*d4+2] * kv.z;
                    s3 += qreg[4*d4+3] * kv.w;
                }
                sc = ((s0 + s1) + (s2 + s3)) * scale;
            }
            Ps[qi*PST + kj] = sc;
            tmax = fmaxf(tmax, sc);
        }
        tmax = fmaxf(tmax, __shfl_xor_sync(0xffffffffu, tmax, 1));
        float mn = fmaxf(m, tmax);
        float corr = __expf(m - mn);
        float lsum = 0.f;
        for (int c = 0; c < 64; c++) {
            int kj = half*64 + c;
            float p = __expf(Ps[qi*PST + kj] - mn);
            Ps[qi*PST + kj] = p;
            lsum += p;
        }
        l = l * corr + lsum;
        m = mn;
#pragma unroll
        for (int d = 0; d < 32; d++) o[d] *= corr;
        __syncthreads();

        // PV
        for (int kj = 0; kj < 128; kj++) {
            float p = Ps[qi*PST + kj];
            if (p != 0.f) {
                const float* vr = &Vs[kj*KST + half*32];
#pragma unroll
                for (int d4 = 0; d4 < 8; d4++) {
                    float4 vv = *(const float4*)(vr + 4*d4);
                    o[4*d4]   += p * vv.x;
                    o[4*d4+1] += p * vv.y;
                    o[4*d4+2] += p * vv.z;
                    o[4*d4+3] += p * vv.w;
                }
            }
        }
    }

    // ---- finalize ----
    float lt = l + __shfl_xor_sync(0xffffffffu, l, 1);
    float inv = 1.0f / lt;
    size_t obase = ((size_t)b * Ss + i) * Dd + h * DK + half * 32;
#pragma unroll
    for (int d = 0; d < 32; d++) {
        float val = o[d] * inv;
        bf16 hv = __float2bfloat16(val);
        oh[obase + d] = hv;
        ol[obase + d] = __float2bfloat16(val - __bfloat162float(hv));
    }
}

// ---------------- launch ----------------
extern "C" void kernel_launch(void* const* d_in, const int* in_sizes, int n_in,
                              void* d_out, int out_size) {
    const float* x   = (const float*)d_in[0];
    const int*   msk = (const int*)  d_in[1];
    const float* Wq  = (const float*)d_in[2],  *bq  = (const float*)d_in[3];
    const float* Wk  = (const float*)d_in[4],  *bk  = (const float*)d_in[5];
    const float* Wv  = (const float*)d_in[6],  *bv  = (const float*)d_in[7];
    const float* Wo  = (const float*)d_in[8],  *bo  = (const float*)d_in[9];
    const float* W1  = (const float*)d_in[10], *bf1 = (const float*)d_in[11];
    const float* W2  = (const float*)d_in[12], *bf2 = (const float*)d_in[13];
    const float* g1  = (const float*)d_in[14], *bl1 = (const float*)d_in[15];
    const float* g2  = (const float*)d_in[16], *bl2 = (const float*)d_in[17];
    float* out = (float*)d_out;

    float *qkv_, *x1_, *bcat_;
    bf16 *sah, *sal, *sfh, *sfl, *wth, *wtl;
    cudaGetSymbolAddress((void**)&qkv_, g_qkv);
    cudaGetSymbolAddress((void**)&x1_,  g_x1);
    cudaGetSymbolAddress((void**)&bcat_,g_bcat);
    cudaGetSymbolAddress((void**)&sah,  g_sa_h);
    cudaGetSymbolAddress((void**)&sal,  g_sa_l);
    cudaGetSymbolAddress((void**)&sfh,  g_sf_h);
    cudaGetSymbolAddress((void**)&sfl,  g_sf_l);
    cudaGetSymbolAddress((void**)&wth,  g_wth);
    cudaGetSymbolAddress((void**)&wtl,  g_wtl);

    cudaFuncSetAttribute(bgemm_mma<false, false, false>,
                         cudaFuncAttributeMaxDynamicSharedMemorySize, GEMM_SMEM);
    cudaFuncSetAttribute(bgemm_mma<false, true, false>,
                         cudaFuncAttributeMaxDynamicSharedMemorySize, GEMM_SMEM);
    cudaFuncSetAttribute(bgemm_mma<true, false, true>,
                         cudaFuncAttributeMaxDynamicSharedMemorySize, GEMM_SMEM);
    cudaFuncSetAttribute(attn2_kernel,
                         cudaFuncAttributeMaxDynamicSharedMemorySize, ATT_SMEM);

    dim3 wblk(32, 8);

    // pre-LN 1 -> split(n)
    ln_split_kernel<<<ROWS, 256>>>(x, g1, bl1, sah, sal);

    // fused QKV: Wt = [3072][1024]
    bcat_kernel<<<12, 256>>>(bq, bk, bv, bcat_);
    wtsplit3_kernel<<<dim3(Dd/32, Dd/32, 3), wblk>>>(Wq, Wk, Wv, wth, wtl);
    bgemm_mma<false, false, false><<<dim3(3*Dd/128, ROWS/128), 256, GEMM_SMEM>>>(
        sah, sal, wth, wtl, bcat_, nullptr, qkv_, nullptr, nullptr, ROWS, 3*Dd, Dd);

    // sparse flash attention -> split(o)
    attn2_kernel<<<dim3(Ss/128, Hh, Bb), 256, ATT_SMEM>>>(qkv_, msk, sah, sal);

    // output projection + residual -> x1
    wtsplit_kernel<<<dim3(Dd/32, Dd/32), wblk>>>(Wo, wth, wtl, Dd, Dd, 0);
    bgemm_mma<false, true, false><<<dim3(Dd/128, ROWS/128), 256, GEMM_SMEM>>>(
        sah, sal, wth, wtl, bo, x, x1_, nullptr, nullptr, ROWS, Dd, Dd);

    // pre-LN 2 -> split(n2)
    ln_split_kernel<<<ROWS, 256>>>(x1_, g2, bl2, sah, sal);

    // FFN up + GELU -> split(ff)
    wtsplit_kernel<<<dim3(FFd/32, Dd/32), wblk>>>(W1, wth, wtl, Dd, FFd, 0);
    bgemm_mma<true, false, true><<<dim3(FFd/128, ROWS/128), 256, GEMM_SMEM>>>(
        sah, sal, wth, wtl, bf1, nullptr, nullptr, sfh, sfl, ROWS, FFd, Dd);

    // FFN down + residual -> out
    wtsplit_kernel<<<dim3(Dd/32, FFd/32), wblk>>>(W2, wth, wtl, FFd, Dd, 0);
    bgemm_mma<false, true, false><<<dim3(Dd/128, ROWS/128), 256, GEMM_SMEM>>>(
        sfh, sfl, wth, wtl, bf2, x1_, out, nullptr, nullptr, ROWS, Dd, FFd);
}

// round 8
// speedup vs baseline: 2.3400x; 1.0983x over previous
#include <cuda_runtime.h>
#include <cuda_bf16.h>
#include <math.h>
#include <stdint.h>

#define Bb 2
#define Ss 2048
#define Dd 1024
#define Hh 16
#define DK 64
#define FFd 4096
#define ROWS (Bb*Ss)          // 4096
#define NEGV (-1000000000.0f)
typedef __nv_bfloat16 bf16;

// ---------------- scratch ----------------
__device__ __align__(256) float g_qkv[ROWS*3*Dd];   // fused q|k|v fp32
__device__ __align__(256) float g_x1 [ROWS*Dd];
__device__ __align__(256) bf16  g_sa_h[ROWS*Dd];    // split of n / o / n2 (sequential reuse)
__device__ __align__(256) bf16  g_sa_l[ROWS*Dd];
__device__ __align__(256) bf16  g_sf_h[ROWS*FFd];   // split of ff
__device__ __align__(256) bf16  g_sf_l[ROWS*FFd];
__device__ __align__(256) bf16  g_wth[Dd*FFd];      // transposed+split weight [N][K]
__device__ __align__(256) bf16  g_wtl[Dd*FFd];
__device__ __align__(256) float g_bcat[3*Dd];

__device__ __forceinline__ void split1(float v, bf16* h, bf16* l, size_t idx) {
    bf16 hv = __float2bfloat16(v);
    h[idx] = hv;
    l[idx] = __float2bfloat16(v - __bfloat162float(hv));
}

// ---------------- weight transpose + split: W[K,N] fp32 -> Wt[N,K] bf16 hi/lo ---------
__device__ __forceinline__ void wtsplit_body(const float* __restrict__ W,
                                             bf16* __restrict__ th, bf16* __restrict__ tl,
                                             int K, int N, int rowOff,
                                             float (*tile)[33]) {
    int kk = blockIdx.y * 32, nn = blockIdx.x * 32;
    int tx = threadIdx.x, ty = threadIdx.y;   // 32 x 8
#pragma unroll
    for (int i = 0; i < 4; i++)
        tile[ty + 8*i][tx] = W[(size_t)(kk + ty + 8*i) * N + nn + tx];
    __syncthreads();
#pragma unroll
    for (int i = 0; i < 4; i++) {
        float v = tile[tx][ty + 8*i];         // = W[kk+tx][nn+ty+8i]
        size_t o = (size_t)(rowOff + nn + ty + 8*i) * K + kk + tx;
        split1(v, th, tl, o);
    }
}
__global__ void wtsplit_kernel(const float* __restrict__ W,
                               bf16* __restrict__ th, bf16* __restrict__ tl,
                               int K, int N, int rowOff) {
    __shared__ float tile[32][33];
    wtsplit_body(W, th, tl, K, N, rowOff, tile);
}
__global__ void wtsplit3_kernel(const float* __restrict__ W0, const float* __restrict__ W1,
                                const float* __restrict__ W2,
                                bf16* __restrict__ th, bf16* __restrict__ tl) {
    __shared__ float tile[32][33];
    const float* W = (blockIdx.z == 0) ? W0 : (blockIdx.z == 1) ? W1 : W2;
    wtsplit_body(W, th, tl, Dd, Dd, blockIdx.z * Dd, tile);
}

// ---------------- bias concat for fused QKV ----------------
__global__ void bcat_kernel(const float* __restrict__ bq, const float* __restrict__ bk,
                            const float* __restrict__ bv, float* __restrict__ o) {
    int i = blockIdx.x * 256 + threadIdx.x;
    if (i < 3*Dd)
        o[i] = (i < Dd) ? bq[i] : ((i < 2*Dd) ? bk[i - Dd] : bv[i - 2*Dd]);
}

// ---------------- layernorm (fused split output) ----------------
__global__ void ln_split_kernel(const float* __restrict__ x,
                                const float* __restrict__ g,
                                const float* __restrict__ b,
                                bf16* __restrict__ oh, bf16* __restrict__ ol) {
    int row = blockIdx.x;
    const float* xr = x + (size_t)row * Dd;
    int tid = threadIdx.x;                 // 256 threads
    int lane = tid & 31, warp = tid >> 5;
    __shared__ float red[32];

    float lv[4]; float s = 0.f;
#pragma unroll
    for (int i = 0; i < 4; i++) { lv[i] = xr[tid + i*256]; s += lv[i]; }
#pragma unroll
    for (int off = 16; off; off >>= 1) s += __shfl_down_sync(0xffffffffu, s, off);
    if (lane == 0) red[warp] = s;
    __syncthreads();
    if (tid == 0) { float t = 0.f; for (int w = 0; w < 8; w++) t += red[w]; red[0] = t; }
    __syncthreads();
    float mu = red[0] * (1.0f / Dd);
    __syncthreads();

    float vs = 0.f;
#pragma unroll
    for (int i = 0; i < 4; i++) { float d = lv[i] - mu; vs += d * d; }
#pragma unroll
    for (int off = 16; off; off >>= 1) vs += __shfl_down_sync(0xffffffffu, vs, off);
    if (lane == 0) red[warp] = vs;
    __syncthreads();
    if (tid == 0) { float t = 0.f; for (int w = 0; w < 8; w++) t += red[w]; red[0] = t; }
    __syncthreads();
    float inv = rsqrtf(red[0] * (1.0f / Dd) + 1e-5f);

#pragma unroll
    for (int i = 0; i < 4; i++) {
        int c = tid + i * 256;
        float v = (lv[i] - mu) * inv * g[c] + b[c];
        split1(v, oh, ol, (size_t)row * Dd + c);
    }
}

// ---------------- HMMA split-bf16 GEMM (ldmatrix + cp.async, 2-stage, 2 CTA/SM) ------
#define RS 80
#define ARR (128*RS)
#define STG (4*ARR)
#define NSTAGE 2
#define GEMM_SMEM (NSTAGE*STG)      // 81920 -> 2 CTAs/SM

__device__ __forceinline__ void cp16(uint32_t s, const void* g) {
    asm volatile("cp.async.cg.shared.global [%0], [%1], 16;" :: "r"(s), "l"(g) : "memory");
}
#define LDSM4(r, a) asm volatile( \
    "ldmatrix.sync.aligned.m8n8.x4.shared.b16 {%0,%1,%2,%3}, [%4];" \
    : "=r"((r)[0]), "=r"((r)[1]), "=r"((r)[2]), "=r"((r)[3]) : "r"(a))
#define MMA_OP(d, a, b0, b1) asm volatile( \
    "mma.sync.aligned.m16n8k16.row.col.f32.bf16.bf16.f32 " \
    "{%0,%1,%2,%3}, {%4,%5,%6,%7}, {%8,%9}, {%0,%1,%2,%3};\n" \
    : "+f"((d)[0]), "+f"((d)[1]), "+f"((d)[2]), "+f"((d)[3]) \
    : "r"((a)[0]), "r"((a)[1]), "r"((a)[2]), "r"((a)[3]), "r"(b0), "r"(b1))

template<bool DO_GELU, bool DO_RES, bool OSPLIT>
__global__ __launch_bounds__(256, 2)
void bgemm_mma(const bf16* __restrict__ Ah, const bf16* __restrict__ Al,
               const bf16* __restrict__ Bh, const bf16* __restrict__ Bl,
               const float* __restrict__ bias, const float* __restrict__ res,
               float* __restrict__ C, bf16* __restrict__ Ch, bf16* __restrict__ Cl,
               int M, int N, int K) {
    extern __shared__ __align__(128) char smem[];
    const int tid = threadIdx.x, lane = tid & 31, warp = tid >> 5;
    const int wm = warp >> 2, wn = warp & 3;
    const int rowBase = blockIdx.y * 128, colBase = blockIdx.x * 128;
    const uint32_t sb = (uint32_t)__cvta_generic_to_shared(smem);
    const int NS = K >> 5;

    auto issue = [&](int s) {
        uint32_t st = sb + (uint32_t)(s & 1) * STG;
        int kk = s << 5;
#pragma unroll
        for (int j = 0; j < 2; j++) {
            int c = tid + (j << 8);
            int r = c >> 2, ke = (c & 3) << 3;
            uint32_t dst = st + r * RS + ((c & 3) << 4);
            size_t ga = (size_t)(rowBase + r) * K + kk + ke;
            size_t gb = (size_t)(colBase + r) * K + kk + ke;
            cp16(dst,           Ah + ga);
            cp16(dst +   ARR,   Al + ga);
            cp16(dst + 2*ARR,   Bh + gb);
            cp16(dst + 3*ARR,   Bl + gb);
        }
        asm volatile("cp.async.commit_group;" ::: "memory");
    };

    float acc[4][4][4] = {};

    issue(0); issue(1);

    for (int s = 0; s < NS; s++) {
        if (s + 1 < NS) asm volatile("cp.async.wait_group 1;" ::: "memory");
        else            asm volatile("cp.async.wait_group 0;" ::: "memory");
        __syncthreads();

        uint32_t st = sb + (uint32_t)(s & 1) * STG;
        uint32_t aBase = st + (wm * 64 + (lane & 15)) * RS + ((lane >> 4) << 4);
        uint32_t bBase = st + 2*ARR + (wn * 32 + (lane & 15)) * RS + ((lane >> 4) << 4);
#pragma unroll
        for (int ks = 0; ks < 2; ks++) {
            uint32_t ko = ks * 32;
            uint32_t ah[4][4], alr[4][4], bh[2][4], blr[2][4];
#pragma unroll
            for (int mi = 0; mi < 4; mi++) {
                LDSM4(ah[mi],  aBase + mi * (16*RS) + ko);
                LDSM4(alr[mi], aBase + ARR + mi * (16*RS) + ko);
            }
#pragma unroll
            for (int nb = 0; nb < 2; nb++) {
                LDSM4(bh[nb],  bBase + nb * (16*RS) + ko);
                LDSM4(blr[nb], bBase + ARR + nb * (16*RS) + ko);
            }
#pragma unroll
            for (int mi = 0; mi < 4; mi++)
#pragma unroll
                for (int nb = 0; nb < 2; nb++)
#pragma unroll
                    for (int g = 0; g < 2; g++) {
                        float* d = acc[mi][nb*2 + g];
                        MMA_OP(d, ah[mi],  bh[nb][g],  bh[nb][g+2]);
                        MMA_OP(d, ah[mi],  blr[nb][g], blr[nb][g+2]);
                        MMA_OP(d, alr[mi], bh[nb][g],  bh[nb][g+2]);
                    }
        }
        __syncthreads();
        if (s + 2 < NS) issue(s + 2);
    }

    // ---- epilogue ----
#pragma unroll
    for (int mi = 0; mi < 4; mi++) {
        int r0 = rowBase + wm * 64 + mi * 16 + (lane >> 2);
#pragma unroll
        for (int n8 = 0; n8 < 4; n8++) {
            int c = colBase + wn * 32 + (n8 >> 1) * 16 + (n8 & 1) * 8 + (lane & 3) * 2;
            float* d = acc[mi][n8];
            float b0 = bias[c], b1 = bias[c + 1];
#pragma unroll
            for (int p = 0; p < 2; p++) {
                int r = r0 + p * 8;
                float v0 = d[p*2]     + b0;
                float v1 = d[p*2 + 1] + b1;
                if (DO_GELU) {
                    v0 = 0.5f * v0 * (1.0f + erff(v0 * 0.70710678118654752f));
                    v1 = 0.5f * v1 * (1.0f + erff(v1 * 0.70710678118654752f));
                }
                if (DO_RES) {
                    float2 rr = *(const float2*)(res + (size_t)r * N + c);
                    v0 += rr.x; v1 += rr.y;
                }
                if (OSPLIT) {
                    bf16 h0 = __float2bfloat16(v0), h1 = __float2bfloat16(v1);
                    bf16 l0 = __float2bfloat16(v0 - __bfloat162float(h0));
                    bf16 l1 = __float2bfloat16(v1 - __bfloat162float(h1));
                    uint32_t hp = ((uint32_t)*(uint16_t*)&h1 << 16) | *(uint16_t*)&h0;
                    uint32_t lp = ((uint32_t)*(uint16_t*)&l1 << 16) | *(uint16_t*)&l0;
                    *(uint32_t*)(Ch + (size_t)r * N + c) = hp;
                    *(uint32_t*)(Cl + (size_t)r * N + c) = lp;
                } else {
                    *(float2*)(C + (size_t)r * N + c) = make_float2(v0, v1);
                }
            }
        }
    }
}

// ---------------- query-tile flash sparse attention ----------------
#define KST 68
#define PST 130
#define ATT_SMEM ((2*128*KST + 128*PST) * 4)   // 136192 B

__global__ __launch_bounds__(256)
void attn2_kernel(const float* __restrict__ qkv, const int* __restrict__ mask,
                  bf16* __restrict__ oh, bf16* __restrict__ ol) {
    extern __shared__ float sm[];
    float* Ks = sm;
    float* Vs = sm + 128*KST;
    float* Ps = sm + 2*128*KST;

    const int qb = blockIdx.x, h = blockIdx.y, b = blockIdx.z;
    const int tid = threadIdx.x;
    const int qi = tid >> 1, half = tid & 1;
    const int i = qb * 128 + qi;
    const float scale = 0.125f;
    const int* mrow = mask + (size_t)i * Ss;

    float qreg[64];
    {
        const float* qptr = qkv + ((size_t)b * Ss + i) * (3*Dd) + h * DK;
#pragma unroll
        for (int d4 = 0; d4 < 16; d4++) {
            float4 v = *(const float4*)(qptr + 4*d4);
            qreg[4*d4] = v.x; qreg[4*d4+1] = v.y; qreg[4*d4+2] = v.z; qreg[4*d4+3] = v.w;
        }
    }

    float m = -3.0e38f, l = 0.f;
    float o[32];
#pragma unroll
    for (int d = 0; d < 32; d++) o[d] = 0.f;

    for (int mm = 2; mm <= qb; mm++) {
        int j = i - 128 * mm;
        const float* kr = qkv + ((size_t)b * Ss + j) * (3*Dd) + Dd + h * DK + half * 32;
        float s0 = 0, s1 = 0, s2 = 0, s3 = 0;
#pragma unroll
        for (int d4 = 0; d4 < 8; d4++) {
            float4 kv = *(const float4*)(kr + 4*d4);
            s0 += qreg[half*32 + 4*d4]     * kv.x;
            s1 += qreg[half*32 + 4*d4 + 1] * kv.y;
            s2 += qreg[half*32 + 4*d4 + 2] * kv.z;
            s3 += qreg[half*32 + 4*d4 + 3] * kv.w;
        }
        float sc = (s0 + s1) + (s2 + s3);
        sc += __shfl_xor_sync(0xffffffffu, sc, 1);
        sc *= scale;
        if (mrow[j] == 0) sc = NEGV;

        float mn = fmaxf(m, sc);
        float corr = __expf(m - mn);
        float p = __expf(sc - mn);
        l = l * corr + (half ? 0.f : p);
        m = mn;
        const float* vr = qkv + ((size_t)b * Ss + j) * (3*Dd) + 2*Dd + h * DK + half * 32;
#pragma unroll
        for (int d4 = 0; d4 < 8; d4++) {
            float4 vv = *(const float4*)(vr + 4*d4);
            o[4*d4]   = o[4*d4]   * corr + p * vv.x;
            o[4*d4+1] = o[4*d4+1] * corr + p * vv.y;
            o[4*d4+2] = o[4*d4+2] * corr + p * vv.z;
            o[4*d4+3] = o[4*d4+3] * corr + p * vv.w;
        }
    }

    int t0 = (qb > 0) ? qb - 1 : 0;
    for (int t = t0; t <= qb; t++) {
        __syncthreads();
        const float* gk = qkv + ((size_t)b * Ss + t*128) * (3*Dd) + Dd + h * DK;
        const float* gv = gk + Dd;
        for (int idx = tid; idx < 8192; idx += 256) {
            int r = idx >> 6, d = idx & 63;
            Ks[r*KST + d] = gk[(size_t)r * (3*Dd) + d];
            Vs[r*KST + d] = gv[(size_t)r * (3*Dd) + d];
        }
        __syncthreads();

        float tmax = -3.0e38f;
        int jbase = t * 128;
        for (int c = 0; c < 64; c++) {
            int kj = half*64 + c;
            bool allowed = (t == qb) ? (kj <= qi) : (kj >= qi);
            float sc = NEGV;
            if (allowed && mrow[jbase + kj] != 0) {
                const float* kr = &Ks[kj*KST];
                float s0 = 0, s1 = 0, s2 = 0, s3 = 0;
#pragma unroll
                for (int d4 = 0; d4 < 16; d4++) {
                    float4 kv = *(const float4*)(kr + 4*d4);
                    s0 += qreg[4*d4]   * kv.x;
                    s1 += qreg[4*d4+1] * kv.y;
                    s2 += qreg[4*d4+2] * kv.z;
                    s3 += qreg[4*d4+3] * kv.w;
                }
                sc = ((s0 + s1) + (s2 + s3)) * scale;
            }
            Ps[qi*PST + kj] = sc;
            tmax = fmaxf(tmax, sc);
        }
        tmax = fmaxf(tmax, __shfl_xor_sync(0xffffffffu, tmax, 1));
        float mn = fmaxf(m, tmax);
        float corr = __expf(m - mn);
        float lsum = 0.f;
        for (int c = 0; c < 64; c++) {
            int kj = half*64 + c;
            float p = __expf(Ps[qi*PST + kj] - mn);
            Ps[qi*PST + kj] = p;
            lsum += p;
        }
        l = l * corr + lsum;
        m = mn;
#pragma unroll
        for (int d = 0; d < 32; d++) o[d] *= corr;
        __syncthreads();

        for (int kj = 0; kj < 128; kj++) {
            float p = Ps[qi*PST + kj];
            if (p != 0.f) {
                const float* vr = &Vs[kj*KST + half*32];
#pragma unroll
                for (int d4 = 0; d4 < 8; d4++) {
                    float4 vv = *(const float4*)(vr + 4*d4);
                    o[4*d4]   += p * vv.x;
                    o[4*d4+1] += p * vv.y;
                    o[4*d4+2] += p * vv.z;
                    o[4*d4+3] += p * vv.w;
                }
            }
        }
    }

    float lt = l + __shfl_xor_sync(0xffffffffu, l, 1);
    float inv = 1.0f / lt;
    size_t obase = ((size_t)b * Ss + i) * Dd + h * DK + half * 32;
#pragma unroll
    for (int d = 0; d < 32; d++) {
        float val = o[d] * inv;
        bf16 hv = __float2bfloat16(val);
        oh[obase + d] = hv;
        ol[obase + d] = __float2bfloat16(val - __bfloat162float(hv));
    }
}

// ---------------- launch ----------------
extern "C" void kernel_launch(void* const* d_in, const int* in_sizes, int n_in,
                              void* d_out, int out_size) {
    const float* x   = (const float*)d_in[0];
    const int*   msk = (const int*)  d_in[1];
    const float* Wq  = (const float*)d_in[2],  *bq  = (const float*)d_in[3];
    const float* Wk  = (const float*)d_in[4],  *bk  = (const float*)d_in[5];
    const float* Wv  = (const float*)d_in[6],  *bv  = (const float*)d_in[7];
    const float* Wo  = (const float*)d_in[8],  *bo  = (const float*)d_in[9];
    const float* W1  = (const float*)d_in[10], *bf1 = (const float*)d_in[11];
    const float* W2  = (const float*)d_in[12], *bf2 = (const float*)d_in[13];
    const float* g1  = (const float*)d_in[14], *bl1 = (const float*)d_in[15];
    const float* g2  = (const float*)d_in[16], *bl2 = (const float*)d_in[17];
    float* out = (float*)d_out;

    float *qkv_, *x1_, *bcat_;
    bf16 *sah, *sal, *sfh, *sfl, *wth, *wtl;
    cudaGetSymbolAddress((void**)&qkv_, g_qkv);
    cudaGetSymbolAddress((void**)&x1_,  g_x1);
    cudaGetSymbolAddress((void**)&bcat_,g_bcat);
    cudaGetSymbolAddress((void**)&sah,  g_sa_h);
    cudaGetSymbolAddress((void**)&sal,  g_sa_l);
    cudaGetSymbolAddress((void**)&sfh,  g_sf_h);
    cudaGetSymbolAddress((void**)&sfl,  g_sf_l);
    cudaGetSymbolAddress((void**)&wth,  g_wth);
    cudaGetSymbolAddress((void**)&wtl,  g_wtl);

    cudaFuncSetAttribute(bgemm_mma<false, false, false>,
                         cudaFuncAttributeMaxDynamicSharedMemorySize, GEMM_SMEM);
    cudaFuncSetAttribute(bgemm_mma<false, true, false>,
                         cudaFuncAttributeMaxDynamicSharedMemorySize, GEMM_SMEM);
    cudaFuncSetAttribute(bgemm_mma<true, false, true>,
                         cudaFuncAttributeMaxDynamicSharedMemorySize, GEMM_SMEM);
    cudaFuncSetAttribute(attn2_kernel,
                         cudaFuncAttributeMaxDynamicSharedMemorySize, ATT_SMEM);

    dim3 wblk(32, 8);

    // pre-LN 1 -> split(n)
    ln_split_kernel<<<ROWS, 256>>>(x, g1, bl1, sah, sal);

    // fused QKV: Wt = [3072][1024]
    bcat_kernel<<<12, 256>>>(bq, bk, bv, bcat_);
    wtsplit3_kernel<<<dim3(Dd/32, Dd/32, 3), wblk>>>(Wq, Wk, Wv, wth, wtl);
    bgemm_mma<false, false, false><<<dim3(3*Dd/128, ROWS/128), 256, GEMM_SMEM>>>(
        sah, sal, wth, wtl, bcat_, nullptr, qkv_, nullptr, nullptr, ROWS, 3*Dd, Dd);

    // sparse flash attention -> split(o)
    attn2_kernel<<<dim3(Ss/128, Hh, Bb), 256, ATT_SMEM>>>(qkv_, msk, sah, sal);

    // output projection + residual -> x1
    wtsplit_kernel<<<dim3(Dd/32, Dd/32), wblk>>>(Wo, wth, wtl, Dd, Dd, 0);
    bgemm_mma<false, true, false><<<dim3(Dd/128, ROWS/128), 256, GEMM_SMEM>>>(
        sah, sal, wth, wtl, bo, x, x1_, nullptr, nullptr, ROWS, Dd, Dd);

    // pre-LN 2 -> split(n2)
    ln_split_kernel<<<ROWS, 256>>>(x1_, g2, bl2, sah, sal);

    // FFN up + GELU -> split(ff)
    wtsplit_kernel<<<dim3(FFd/32, Dd/32), wblk>>>(W1, wth, wtl, Dd, FFd, 0);
    bgemm_mma<true, false, true><<<dim3(FFd/128, ROWS/128), 256, GEMM_SMEM>>>(
        sah, sal, wth, wtl, bf1, nullptr, nullptr, sfh, sfl, ROWS, FFd, Dd);

    // FFN down + residual -> out
    wtsplit_kernel<<<dim3(Dd/32, FFd/32), wblk>>>(W2, wth, wtl, FFd, Dd, 0);
    bgemm_mma<false, true, false><<<dim3(Dd/128, ROWS/128), 256, GEMM_SMEM>>>(
        sfh, sfl, wth, wtl, bf2, x1_, out, nullptr, nullptr, ROWS, Dd, FFd);
}

// round 10
// speedup vs baseline: 2.8982x; 1.2385x over previous
#include <cuda_runtime.h>
#include <cuda_fp16.h>
#include <math.h>
#include <stdint.h>

#define Bb 2
#define Ss 2048
#define Dd 1024
#define Hh 16
#define DK 64
#define FFd 4096
#define ROWS (Bb*Ss)          // 4096
#define NEGV (-1000000000.0f)
typedef __half f16;

// ---------------- scratch ----------------
__device__ __align__(256) float g_qkv[ROWS*3*Dd];   // fused q|k|v fp32
__device__ __align__(256) float g_x1 [ROWS*Dd];
__device__ __align__(256) f16   g_sa_h[ROWS*Dd];    // split of n / o / n2 (sequential reuse)
__device__ __align__(256) f16   g_sa_l[ROWS*Dd];
__device__ __align__(256) f16   g_sf_h[ROWS*FFd];   // split of ff
__device__ __align__(256) f16   g_sf_l[ROWS*FFd];
__device__ __align__(256) f16   g_wt [Dd*FFd];      // transposed fp16 weight [N][K]
__device__ __align__(256) float g_bcat[3*Dd];

__device__ __forceinline__ void split1(float v, f16* h, f16* l, size_t idx) {
    f16 hv = __float2half_rn(v);
    h[idx] = hv;
    l[idx] = __float2half_rn(v - __half2float(hv));
}

// ---------------- weight transpose + fp16 convert: W[K,N] -> Wt[N,K] ----------------
__device__ __forceinline__ void wtcvt_body(const float* __restrict__ W,
                                           f16* __restrict__ t,
                                           int K, int N, int rowOff,
                                           float (*tile)[33]) {
    int kk = blockIdx.y * 32, nn = blockIdx.x * 32;
    int tx = threadIdx.x, ty = threadIdx.y;   // 32 x 8
#pragma unroll
    for (int i = 0; i < 4; i++)
        tile[ty + 8*i][tx] = W[(size_t)(kk + ty + 8*i) * N + nn + tx];
    __syncthreads();
#pragma unroll
    for (int i = 0; i < 4; i++) {
        float v = tile[tx][ty + 8*i];
        t[(size_t)(rowOff + nn + ty + 8*i) * K + kk + tx] = __float2half_rn(v);
    }
}
__global__ void wtcvt_kernel(const float* __restrict__ W, f16* __restrict__ t,
                             int K, int N, int rowOff) {
    __shared__ float tile[32][33];
    wtcvt_body(W, t, K, N, rowOff, tile);
}
__global__ void wtcvt3_kernel(const float* __restrict__ W0, const float* __restrict__ W1,
                              const float* __restrict__ W2, f16* __restrict__ t) {
    __shared__ float tile[32][33];
    const float* W = (blockIdx.z == 0) ? W0 : (blockIdx.z == 1) ? W1 : W2;
    wtcvt_body(W, t, Dd, Dd, blockIdx.z * Dd, tile);
}

// ---------------- bias concat for fused QKV ----------------
__global__ void bcat_kernel(const float* __restrict__ bq, const float* __restrict__ bk,
                            const float* __restrict__ bv, float* __restrict__ o) {
    int i = blockIdx.x * 256 + threadIdx.x;
    if (i < 3*Dd)
        o[i] = (i < Dd) ? bq[i] : ((i < 2*Dd) ? bk[i - Dd] : bv[i - 2*Dd]);
}

// ---------------- layernorm (fused fp16 split output) ----------------
__global__ void ln_split_kernel(const float* __restrict__ x,
                                const float* __restrict__ g,
                                const float* __restrict__ b,
                                f16* __restrict__ oh, f16* __restrict__ ol) {
    int row = blockIdx.x;
    const float* xr = x + (size_t)row * Dd;
    int tid = threadIdx.x;                 // 256 threads
    int lane = tid & 31, warp = tid >> 5;
    __shared__ float red[32];

    float lv[4]; float s = 0.f;
#pragma unroll
    for (int i = 0; i < 4; i++) { lv[i] = xr[tid + i*256]; s += lv[i]; }
#pragma unroll
    for (int off = 16; off; off >>= 1) s += __shfl_down_sync(0xffffffffu, s, off);
    if (lane == 0) red[warp] = s;
    __syncthreads();
    if (tid == 0) { float t = 0.f; for (int w = 0; w < 8; w++) t += red[w]; red[0] = t; }
    __syncthreads();
    float mu = red[0] * (1.0f / Dd);
    __syncthreads();

    float vs = 0.f;
#pragma unroll
    for (int i = 0; i < 4; i++) { float d = lv[i] - mu; vs += d * d; }
#pragma unroll
    for (int off = 16; off; off >>= 1) vs += __shfl_down_sync(0xffffffffu, vs, off);
    if (lane == 0) red[warp] = vs;
    __syncthreads();
    if (tid == 0) { float t = 0.f; for (int w = 0; w < 8; w++) t += red[w]; red[0] = t; }
    __syncthreads();
    float inv = rsqrtf(red[0] * (1.0f / Dd) + 1e-5f);

#pragma unroll
    for (int i = 0; i < 4; i++) {
        int c = tid + i * 256;
        float v = (lv[i] - mu) * inv * g[c] + b[c];
        split1(v, oh, ol, (size_t)row * Dd + c);
    }
}

// ---------------- HMMA fp16 2-term GEMM (ldmatrix + cp.async, 3-stage, 2 CTA/SM) ----
// C[M,N] = (Ah+Al)[M,K] @ B[N,K]^T + bias (+gelu) (+res)
#define RS 80
#define ARR (128*RS)                // 10240 B per array
#define STG (3*ARR)                 // 30720 B per stage (Ah|Al|B)
#define NSTAGE 3
#define GEMM_SMEM (NSTAGE*STG)      // 92160 -> 2 CTAs/SM

__device__ __forceinline__ void cp16(uint32_t s, const void* g) {
    asm volatile("cp.async.cg.shared.global [%0], [%1], 16;" :: "r"(s), "l"(g) : "memory");
}
#define LDSM4(r, a) asm volatile( \
    "ldmatrix.sync.aligned.m8n8.x4.shared.b16 {%0,%1,%2,%3}, [%4];" \
    : "=r"((r)[0]), "=r"((r)[1]), "=r"((r)[2]), "=r"((r)[3]) : "r"(a))
#define MMA_OP(d, a, b0, b1) asm volatile( \
    "mma.sync.aligned.m16n8k16.row.col.f32.f16.f16.f32 " \
    "{%0,%1,%2,%3}, {%4,%5,%6,%7}, {%8,%9}, {%0,%1,%2,%3};\n" \
    : "+f"((d)[0]), "+f"((d)[1]), "+f"((d)[2]), "+f"((d)[3]) \
    : "r"((a)[0]), "r"((a)[1]), "r"((a)[2]), "r"((a)[3]), "r"(b0), "r"(b1))

template<bool DO_GELU, bool DO_RES, bool OSPLIT>
__global__ __launch_bounds__(256, 2)
void bgemm_mma(const f16* __restrict__ Ah, const f16* __restrict__ Al,
               const f16* __restrict__ B,
               const float* __restrict__ bias, const float* __restrict__ res,
               float* __restrict__ C, f16* __restrict__ Ch, f16* __restrict__ Cl,
               int M, int N, int K) {
    extern __shared__ __align__(128) char smem[];
    const int tid = threadIdx.x, lane = tid & 31, warp = tid >> 5;
    const int wm = warp >> 2, wn = warp & 3;
    const int rowBase = blockIdx.y * 128, colBase = blockIdx.x * 128;
    const uint32_t sb = (uint32_t)__cvta_generic_to_shared(smem);
    const int NS = K >> 5;

    auto issue = [&](int s) {
        uint32_t st = sb + (uint32_t)(s % 3) * STG;
        int kk = s << 5;
#pragma unroll
        for (int j = 0; j < 2; j++) {
            int c = tid + (j << 8);
            int r = c >> 2, ke = (c & 3) << 3;
            uint32_t dst = st + r * RS + ((c & 3) << 4);
            size_t ga = (size_t)(rowBase + r) * K + kk + ke;
            size_t gb = (size_t)(colBase + r) * K + kk + ke;
            cp16(dst,           Ah + ga);
            cp16(dst +   ARR,   Al + ga);
            cp16(dst + 2*ARR,   B  + gb);
        }
        asm volatile("cp.async.commit_group;" ::: "memory");
    };

    float acc[4][4][4] = {};

    issue(0); issue(1); issue(2);

    for (int s = 0; s < NS; s++) {
        int rem = NS - 1 - s;
        if (rem >= 2)      asm volatile("cp.async.wait_group 2;" ::: "memory");
        else if (rem == 1) asm volatile("cp.async.wait_group 1;" ::: "memory");
        else               asm volatile("cp.async.wait_group 0;" ::: "memory");
        __syncthreads();

        uint32_t st = sb + (uint32_t)(s % 3) * STG;
        uint32_t aBase = st + (wm * 64 + (lane & 15)) * RS + ((lane >> 4) << 4);
        uint32_t bBase = st + 2*ARR + (wn * 32 + (lane & 15)) * RS + ((lane >> 4) << 4);
#pragma unroll
        for (int ks = 0; ks < 2; ks++) {
            uint32_t ko = ks * 32;
            uint32_t ah[4][4], alr[4][4], bh[2][4];
#pragma unroll
            for (int mi = 0; mi < 4; mi++) {
                LDSM4(ah[mi],  aBase + mi * (16*RS) + ko);
                LDSM4(alr[mi], aBase + ARR + mi * (16*RS) + ko);
            }
#pragma unroll
            for (int nb = 0; nb < 2; nb++)
                LDSM4(bh[nb], bBase + nb * (16*RS) + ko);
#pragma unroll
            for (int mi = 0; mi < 4; mi++)
#pragma unroll
                for (int nb = 0; nb < 2; nb++)
#pragma unroll
                    for (int g = 0; g < 2; g++) {
                        float* d = acc[mi][nb*2 + g];
                        MMA_OP(d, ah[mi],  bh[nb][g], bh[nb][g+2]);
                        MMA_OP(d, alr[mi], bh[nb][g], bh[nb][g+2]);
                    }
        }
        __syncthreads();
        if (s + 3 < NS) issue(s + 3);
    }

    // ---- epilogue ----
#pragma unroll
    for (int mi = 0; mi < 4; mi++) {
        int r0 = rowBase + wm * 64 + mi * 16 + (lane >> 2);
#pragma unroll
        for (int n8 = 0; n8 < 4; n8++) {
            int c = colBase + wn * 32 + (n8 >> 1) * 16 + (n8 & 1) * 8 + (lane & 3) * 2;
            float* d = acc[mi][n8];
            float b0 = bias[c], b1 = bias[c + 1];
#pragma unroll
            for (int p = 0; p < 2; p++) {
                int r = r0 + p * 8;
                float v0 = d[p*2]     + b0;
                float v1 = d[p*2 + 1] + b1;
                if (DO_GELU) {
                    v0 = 0.5f * v0 * (1.0f + erff(v0 * 0.70710678118654752f));
                    v1 = 0.5f * v1 * (1.0f + erff(v1 * 0.70710678118654752f));
                }
                if (DO_RES) {
                    float2 rr = *(const float2*)(res + (size_t)r * N + c);
                    v0 += rr.x; v1 += rr.y;
                }
                if (OSPLIT) {
                    f16 h0 = __float2half_rn(v0), h1 = __float2half_rn(v1);
                    f16 l0 = __float2half_rn(v0 - __half2float(h0));
                    f16 l1 = __float2half_rn(v1 - __half2float(h1));
                    uint32_t hp = ((uint32_t)*(uint16_t*)&h1 << 16) | *(uint16_t*)&h0;
                    uint32_t lp = ((uint32_t)*(uint16_t*)&l1 << 16) | *(uint16_t*)&l0;
                    *(uint32_t*)(Ch + (size_t)r * N + c) = hp;
                    *(uint32_t*)(Cl + (size_t)r * N + c) = lp;
                } else {
                    *(float2*)(C + (size_t)r * N + c) = make_float2(v0, v1);
                }
            }
        }
    }
}

// ---------------- query-tile flash sparse attention ----------------
#define KST 68
#define PST 130
#define ATT_SMEM ((2*128*KST + 128*PST) * 4)   // 136192 B

__global__ __launch_bounds__(256)
void attn2_kernel(const float* __restrict__ qkv, const int* __restrict__ mask,
                  f16* __restrict__ oh, f16* __restrict__ ol) {
    extern __shared__ float sm[];
    float* Ks = sm;
    float* Vs = sm + 128*KST;
    float* Ps = sm + 2*128*KST;

    const int qb = blockIdx.x, h = blockIdx.y, b = blockIdx.z;
    const int tid = threadIdx.x;
    const int qi = tid >> 1, half = tid & 1;
    const int i = qb * 128 + qi;
    const float scale = 0.125f;
    const int* mrow = mask + (size_t)i * Ss;

    float qreg[64];
    {
        const float* qptr = qkv + ((size_t)b * Ss + i) * (3*Dd) + h * DK;
#pragma unroll
        for (int d4 = 0; d4 < 16; d4++) {
            float4 v = *(const float4*)(qptr + 4*d4);
            qreg[4*d4] = v.x; qreg[4*d4+1] = v.y; qreg[4*d4+2] = v.z; qreg[4*d4+3] = v.w;
        }
    }

    float m = -3.0e38f, l = 0.f;
    float o[32];
#pragma unroll
    for (int d = 0; d < 32; d++) o[d] = 0.f;

    for (int mm = 2; mm <= qb; mm++) {
        int j = i - 128 * mm;
        const float* kr = qkv + ((size_t)b * Ss + j) * (3*Dd) + Dd + h * DK + half * 32;
        float s0 = 0, s1 = 0, s2 = 0, s3 = 0;
#pragma unroll
        for (int d4 = 0; d4 < 8; d4++) {
            float4 kv = *(const float4*)(kr + 4*d4);
            s0 += qreg[half*32 + 4*d4]     * kv.x;
            s1 += qreg[half*32 + 4*d4 + 1] * kv.y;
            s2 += qreg[half*32 + 4*d4 + 2] * kv.z;
            s3 += qreg[half*32 + 4*d4 + 3] * kv.w;
        }
        float sc = (s0 + s1) + (s2 + s3);
        sc += __shfl_xor_sync(0xffffffffu, sc, 1);
        sc *= scale;
        if (mrow[j] == 0) sc = NEGV;

        float mn = fmaxf(m, sc);
        float corr = __expf(m - mn);
        float p = __expf(sc - mn);
        l = l * corr + (half ? 0.f : p);
        m = mn;
        const float* vr = qkv + ((size_t)b * Ss + j) * (3*Dd) + 2*Dd + h * DK + half * 32;
#pragma unroll
        for (int d4 = 0; d4 < 8; d4++) {
            float4 vv = *(const float4*)(vr + 4*d4);
            o[4*d4]   = o[4*d4]   * corr + p * vv.x;
            o[4*d4+1] = o[4*d4+1] * corr + p * vv.y;
            o[4*d4+2] = o[4*d4+2] * corr + p * vv.z;
            o[4*d4+3] = o[4*d4+3] * corr + p * vv.w;
        }
    }

    int t0 = (qb > 0) ? qb - 1 : 0;
    for (int t = t0; t <= qb; t++) {
        __syncthreads();
        const float* gk = qkv + ((size_t)b * Ss + t*128) * (3*Dd) + Dd + h * DK;
        const float* gv = gk + Dd;
        for (int idx = tid; idx < 8192; idx += 256) {
            int r = idx >> 6, d = idx & 63;
            Ks[r*KST + d] = gk[(size_t)r * (3*Dd) + d];
            Vs[r*KST + d] = gv[(size_t)r * (3*Dd) + d];
        }
        __syncthreads();

        float tmax = -3.0e38f;
        int jbase = t * 128;
        for (int c = 0; c < 64; c++) {
            int kj = half*64 + c;
            bool allowed = (t == qb) ? (kj <= qi) : (kj >= qi);
            float sc = NEGV;
            if (allowed && mrow[jbase + kj] != 0) {
                const float* kr = &Ks[kj*KST];
                float s0 = 0, s1 = 0, s2 = 0, s3 = 0;
#pragma unroll
                for (int d4 = 0; d4 < 16; d4++) {
                    float4 kv = *(const float4*)(kr + 4*d4);
                    s0 += qreg[4*d4]   * kv.x;
                    s1 += qreg[4*d4+1] * kv.y;
                    s2 += qreg[4*d4+2] * kv.z;
                    s3 += qreg[4*d4+3] * kv.w;
                }
                sc = ((s0 + s1) + (s2 + s3)) * scale;
            }
            Ps[qi*PST + kj] = sc;
            tmax = fmaxf(tmax, sc);
        }
        tmax = fmaxf(tmax, __shfl_xor_sync(0xffffffffu, tmax, 1));
        float mn = fmaxf(m, tmax);
        float corr = __expf(m - mn);
        float lsum = 0.f;
        for (int c = 0; c < 64; c++) {
            int kj = half*64 + c;
            float p = __expf(Ps[qi*PST + kj] - mn);
            Ps[qi*PST + kj] = p;
            lsum += p;
        }
        l = l * corr + lsum;
        m = mn;
#pragma unroll
        for (int d = 0; d < 32; d++) o[d] *= corr;
        __syncthreads();

        for (int kj = 0; kj < 128; kj++) {
            float p = Ps[qi*PST + kj];
            if (p != 0.f) {
                const float* vr = &Vs[kj*KST + half*32];
#pragma unroll
                for (int d4 = 0; d4 < 8; d4++) {
                    float4 vv = *(const float4*)(vr + 4*d4);
                    o[4*d4]   += p * vv.x;
                    o[4*d4+1] += p * vv.y;
                    o[4*d4+2] += p * vv.z;
                    o[4*d4+3] += p * vv.w;
                }
            }
        }
    }

    float lt = l + __shfl_xor_sync(0xffffffffu, l, 1);
    float inv = 1.0f / lt;
    size_t obase = ((size_t)b * Ss + i) * Dd + h * DK + half * 32;
#pragma unroll
    for (int d = 0; d < 32; d++) {
        float val = o[d] * inv;
        f16 hv = __float2half_rn(val);
        oh[obase + d] = hv;
        ol[obase + d] = __float2half_rn(val - __half2float(hv));
    }
}

// ---------------- launch ----------------
extern "C" void kernel_launch(void* const* d_in, const int* in_sizes, int n_in,
                              void* d_out, int out_size) {
    const float* x   = (const float*)d_in[0];
    const int*   msk = (const int*)  d_in[1];
    const float* Wq  = (const float*)d_in[2],  *bq  = (const float*)d_in[3];
    const float* Wk  = (const float*)d_in[4],  *bk  = (const float*)d_in[5];
    const float* Wv  = (const float*)d_in[6],  *bv  = (const float*)d_in[7];
    const float* Wo  = (const float*)d_in[8],  *bo  = (const float*)d_in[9];
    const float* W1  = (const float*)d_in[10], *bf1 = (const float*)d_in[11];
    const float* W2  = (const float*)d_in[12], *bf2 = (const float*)d_in[13];
    const float* g1  = (const float*)d_in[14], *bl1 = (const float*)d_in[15];
    const float* g2  = (const float*)d_in[16], *bl2 = (const float*)d_in[17];
    float* out = (float*)d_out;

    float *qkv_, *x1_, *bcat_;
    f16 *sah, *sal, *sfh, *sfl, *wt;
    cudaGetSymbolAddress((void**)&qkv_, g_qkv);
    cudaGetSymbolAddress((void**)&x1_,  g_x1);
    cudaGetSymbolAddress((void**)&bcat_,g_bcat);
    cudaGetSymbolAddress((void**)&sah,  g_sa_h);
    cudaGetSymbolAddress((void**)&sal,  g_sa_l);
    cudaGetSymbolAddress((void**)&sfh,  g_sf_h);
    cudaGetSymbolAddress((void**)&sfl,  g_sf_l);
    cudaGetSymbolAddress((void**)&wt,   g_wt);

    cudaFuncSetAttribute(bgemm_mma<false, false, false>,
                         cudaFuncAttributeMaxDynamicSharedMemorySize, GEMM_SMEM);
    cudaFuncSetAttribute(bgemm_mma<false, true, false>,
                         cudaFuncAttributeMaxDynamicSharedMemorySize, GEMM_SMEM);
    cudaFuncSetAttribute(bgemm_mma<true, false, true>,
                         cudaFuncAttributeMaxDynamicSharedMemorySize, GEMM_SMEM);
    cudaFuncSetAttribute(attn2_kernel,
                         cudaFuncAttributeMaxDynamicSharedMemorySize, ATT_SMEM);

    dim3 wblk(32, 8);

    // pre-LN 1 -> split(n)
    ln_split_kernel<<<ROWS, 256>>>(x, g1, bl1, sah, sal);

    // fused QKV: Wt = [3072][1024]
    bcat_kernel<<<12, 256>>>(bq, bk, bv, bcat_);
    wtcvt3_kernel<<<dim3(Dd/32, Dd/32, 3), wblk>>>(Wq, Wk, Wv, wt);
    bgemm_mma<false, false, false><<<dim3(3*Dd/128, ROWS/128), 256, GEMM_SMEM>>>(
        sah, sal, wt, bcat_, nullptr, qkv_, nullptr, nullptr, ROWS, 3*Dd, Dd);

    // sparse flash attention -> split(o)
    attn2_kernel<<<dim3(Ss/128, Hh, Bb), 256, ATT_SMEM>>>(qkv_, msk, sah, sal);

    // output projection + residual -> x1
    wtcvt_kernel<<<dim3(Dd/32, Dd/32), wblk>>>(Wo, wt, Dd, Dd, 0);
    bgemm_mma<false, true, false><<<dim3(Dd/128, ROWS/128), 256, GEMM_SMEM>>>(
        sah, sal, wt, bo, x, x1_, nullptr, nullptr, ROWS, Dd, Dd);

    // pre-LN 2 -> split(n2)
    ln_split_kernel<<<ROWS, 256>>>(x1_, g2, bl2, sah, sal);

    // FFN up + GELU -> split(ff)
    wtcvt_kernel<<<dim3(FFd/32, Dd/32), wblk>>>(W1, wt, Dd, FFd, 0);
    bgemm_mma<true, false, true><<<dim3(FFd/128, ROWS/128), 256, GEMM_SMEM>>>(
        sah, sal, wt, bf1, nullptr, nullptr, sfh, sfl, ROWS, FFd, Dd);

    // FFN down + residual -> out
    wtcvt_kernel<<<dim3(Dd/32, FFd/32), wblk>>>(W2, wt, FFd, Dd, 0);
    bgemm_mma<false, true, false><<<dim3(Dd/128, ROWS/128), 256, GEMM_SMEM>>>(
        sfh, sfl, wt, bf2, x1_, out, nullptr, nullptr, ROWS, Dd, FFd);
}